// round 6
// baseline (speedup 1.0000x reference)
#include <cuda_runtime.h>
#include <cuda_bf16.h>

#define SS 256
#define CC 128
#define HH 4
#define DD 32
#define TT (SS*SS)

typedef unsigned int u32;

// ---------------- global scratch (no allocations allowed) ----------------
#define NQ (SS*HH*SS*DD)   // 8,388,608
__device__ __nv_bfloat16 g_Qh[NQ], g_Ql[NQ];
__device__ __nv_bfloat16 g_Kh[NQ], g_Kl[NQ];
__device__ __nv_bfloat16 g_Vh[NQ], g_Vl[NQ];
__device__ float         g_G [(size_t)TT*CC];
__device__ __nv_bfloat16 g_Oh[(size_t)TT*CC], g_Ol[(size_t)TT*CC];
__device__ __nv_bfloat16 g_Wqg_h[2*CC*CC], g_Wqg_l[2*CC*CC];
__device__ __nv_bfloat16 g_Wkv_h[2*CC*CC], g_Wkv_l[2*CC*CC];
__device__ __nv_bfloat16 g_Wo_h [CC*CC],   g_Wo_l [CC*CC];

__device__ __forceinline__ void split2(float v, __nv_bfloat16& h, __nv_bfloat16& l) {
    h = __float2bfloat16(v);
    l = __float2bfloat16(v - __bfloat162float(h));
}

__device__ __forceinline__ void mma_bf16(float* d, const u32* a, const u32* b) {
    asm volatile(
      "mma.sync.aligned.m16n8k16.row.col.f32.bf16.bf16.f32 "
      "{%0,%1,%2,%3}, {%4,%5,%6,%7}, {%8,%9}, {%0,%1,%2,%3};\n"
      : "+f"(d[0]), "+f"(d[1]), "+f"(d[2]), "+f"(d[3])
      : "r"(a[0]), "r"(a[1]), "r"(a[2]), "r"(a[3]), "r"(b[0]), "r"(b[1]));
}

__device__ __forceinline__ void ldsm4(u32* r, const void* p) {
    u32 a = (u32)__cvta_generic_to_shared(p);
    asm volatile("ldmatrix.sync.aligned.m8n8.x4.shared.b16 {%0,%1,%2,%3}, [%4];"
                 : "=r"(r[0]), "=r"(r[1]), "=r"(r[2]), "=r"(r[3]) : "r"(a));
}
__device__ __forceinline__ void ldsm2(u32* r, const void* p) {
    u32 a = (u32)__cvta_generic_to_shared(p);
    asm volatile("ldmatrix.sync.aligned.m8n8.x2.shared.b16 {%0,%1}, [%2];"
                 : "=r"(r[0]), "=r"(r[1]) : "r"(a));
}

// ---------------- weight prep: fp32 -> split bf16, stacked ----------------
__global__ void prep_w(const float* __restrict__ wq, const float* __restrict__ wk,
                       const float* __restrict__ wv, const float* __restrict__ wg,
                       const float* __restrict__ wo) {
    int i = blockIdx.x * blockDim.x + threadIdx.x;
    if (i >= CC*CC) return;
    split2(wq[i], g_Wqg_h[i],          g_Wqg_l[i]);
    split2(wg[i], g_Wqg_h[CC*CC + i],  g_Wqg_l[CC*CC + i]);
    split2(wk[i], g_Wkv_h[i],          g_Wkv_l[i]);
    split2(wv[i], g_Wkv_h[CC*CC + i],  g_Wkv_l[CC*CC + i]);
    split2(wo[i], g_Wo_h[i],           g_Wo_l[i]);
}

// ---------------- projection GEMM (bf16 3x-split, mma.sync) ----------------
#define AST 72
#define PROJ_SMEM (4*128*AST*2)

template<int MODE>
__global__ void __launch_bounds__(256, 2) proj_kernel(const float* __restrict__ X,
                                                      const float* __restrict__ bias,
                                                      float* __restrict__ outp)
{
    extern __shared__ __nv_bfloat16 sm[];
    __nv_bfloat16* Ah = sm;
    __nv_bfloat16* Al = sm + 128*AST;
    __nv_bfloat16* Bh = sm + 2*128*AST;
    __nv_bfloat16* Bl = sm + 3*128*AST;

    const int tid = threadIdx.x;
    const int lane = tid & 31;
    const int w = tid >> 5;
    const int g = lane >> 2;
    const int tg = lane & 3;
    const int wm = w & 3;
    const int wn = w >> 2;
    const int m0 = blockIdx.x * 128;
    const int n0 = blockIdx.y * 128;

    const __nv_bfloat16 *Wh, *Wl;
    if (MODE == 0)      { Wh = g_Wqg_h; Wl = g_Wqg_l; }
    else if (MODE == 1) { Wh = g_Wkv_h; Wl = g_Wkv_l; }
    else                { Wh = g_Wo_h;  Wl = g_Wo_l;  }

    float acc[2][8][4];
#pragma unroll
    for (int a = 0; a < 2; a++)
#pragma unroll
        for (int b = 0; b < 8; b++)
#pragma unroll
            for (int c = 0; c < 4; c++) acc[a][b][c] = 0.f;

    for (int ks = 0; ks < 2; ks++) {
        const int kbase = ks * 64;
        if (MODE < 2) {
#pragma unroll
            for (int i = 0; i < 8; i++) {
                int lin = tid + 256*i;
                int r = lin >> 4;
                int c = (lin & 15) * 4;
                float4 xv = *(const float4*)(X + (size_t)(m0+r)*CC + kbase + c);
                split2(xv.x, Ah[r*AST+c+0], Al[r*AST+c+0]);
                split2(xv.y, Ah[r*AST+c+1], Al[r*AST+c+1]);
                split2(xv.z, Ah[r*AST+c+2], Al[r*AST+c+2]);
                split2(xv.w, Ah[r*AST+c+3], Al[r*AST+c+3]);
            }
        } else {
#pragma unroll
            for (int i = 0; i < 16; i++) {
                int lin = tid + 256*i;
                int r = lin >> 5;
                int c = (lin & 31) * 2;
                *(u32*)&Ah[r*AST+c] = *(const u32*)(g_Oh + (size_t)(m0+r)*CC + kbase + c);
                *(u32*)&Al[r*AST+c] = *(const u32*)(g_Ol + (size_t)(m0+r)*CC + kbase + c);
            }
        }
#pragma unroll
        for (int i = 0; i < 16; i++) {
            int lin = tid + 256*i;
            int r = lin >> 5;
            int c = (lin & 31) * 2;
            *(u32*)&Bh[r*AST+c] = *(const u32*)(Wh + (size_t)(n0+r)*CC + kbase + c);
            *(u32*)&Bl[r*AST+c] = *(const u32*)(Wl + (size_t)(n0+r)*CC + kbase + c);
        }
        __syncthreads();

#pragma unroll
        for (int k16 = 0; k16 < 4; k16++) {
            const int kk = k16*16 + tg*2;
            u32 ah[2][4], al[2][4];
#pragma unroll
            for (int mt = 0; mt < 2; mt++) {
                int row = wm*32 + mt*16 + g;
                ah[mt][0] = *(u32*)&Ah[ row   *AST + kk];
                ah[mt][1] = *(u32*)&Ah[(row+8)*AST + kk];
                ah[mt][2] = *(u32*)&Ah[ row   *AST + kk + 8];
                ah[mt][3] = *(u32*)&Ah[(row+8)*AST + kk + 8];
                al[mt][0] = *(u32*)&Al[ row   *AST + kk];
                al[mt][1] = *(u32*)&Al[(row+8)*AST + kk];
                al[mt][2] = *(u32*)&Al[ row   *AST + kk + 8];
                al[mt][3] = *(u32*)&Al[(row+8)*AST + kk + 8];
            }
#pragma unroll
            for (int nt = 0; nt < 8; nt++) {
                int n = wn*64 + nt*8 + g;
                u32 bh[2], bl[2];
                bh[0] = *(u32*)&Bh[n*AST + kk];
                bh[1] = *(u32*)&Bh[n*AST + kk + 8];
                bl[0] = *(u32*)&Bl[n*AST + kk];
                bl[1] = *(u32*)&Bl[n*AST + kk + 8];
#pragma unroll
                for (int mt = 0; mt < 2; mt++) {
                    mma_bf16(acc[mt][nt], ah[mt], bh);
                    mma_bf16(acc[mt][nt], ah[mt], bl);
                    mma_bf16(acc[mt][nt], al[mt], bh);
                }
            }
        }
        __syncthreads();
    }

#pragma unroll
    for (int mt = 0; mt < 2; mt++) {
#pragma unroll
        for (int nt = 0; nt < 8; nt++) {
#pragma unroll
            for (int rr = 0; rr < 2; rr++) {
                int m   = m0 + wm*32 + mt*16 + g + rr*8;
                int col = wn*64 + nt*8 + tg*2;
                float y0 = acc[mt][nt][rr*2+0];
                float y1 = acc[mt][nt][rr*2+1];
                if (MODE == 2) {
                    float2 o; o.x = y0 + bias[col]; o.y = y1 + bias[col+1];
                    *(float2*)(outp + (size_t)m*CC + col) = o;
                } else if (blockIdx.y == 0) {
                    if (MODE == 0) { y0 *= 0.17677669529663687f; y1 *= 0.17677669529663687f; }
                    int hh = col >> 5, d = col & 31;
                    int si = m >> 8,  j = m & 255;
                    size_t idx = (((size_t)si*HH + hh)*SS + j)*DD + d;
                    __nv_bfloat162 vh, vl;
                    split2(y0, vh.x, vl.x);
                    split2(y1, vh.y, vl.y);
                    if (MODE == 0) { *(__nv_bfloat162*)&g_Qh[idx] = vh; *(__nv_bfloat162*)&g_Ql[idx] = vl; }
                    else           { *(__nv_bfloat162*)&g_Kh[idx] = vh; *(__nv_bfloat162*)&g_Kl[idx] = vl; }
                } else {
                    if (MODE == 0) {
                        float s0 = 1.f/(1.f + __expf(-(y0 + bias[col])));
                        float s1 = 1.f/(1.f + __expf(-(y1 + bias[col+1])));
                        *(float2*)(g_G + (size_t)m*CC + col) = make_float2(s0, s1);
                    } else {
                        int hh = col >> 5, d = col & 31;
                        int si = m >> 8,  j = m & 255;
                        size_t idx = (((size_t)si*HH + hh)*SS + j)*DD + d;
                        __nv_bfloat162 vh, vl;
                        split2(y0, vh.x, vl.x);
                        split2(y1, vh.y, vl.y);
                        *(__nv_bfloat162*)&g_Vh[idx] = vh;
                        *(__nv_bfloat162*)&g_Vl[idx] = vl;
                    }
                }
            }
        }
    }
}

// ---------------- attention v3: 8 warps, M=32/warp, ldmatrix B-operands ----
// CTA = one (s,h): 256 threads / 8 warps; warp owns 32 q-rows x all 256 keys.
// Keys in 4 chunks of 64 with online softmax; P stays in registers.
#define KST 40
#define VST 264
#define ATTN_SMEM (2*256*KST*2 + 2*32*VST*2 + 256*4)   // 75776 B

__global__ void __launch_bounds__(256, 1) attn_kernel(const float* __restrict__ bias1,
                                                      const float* __restrict__ bias2)
{
    extern __shared__ char smraw[];
    __nv_bfloat16* Ksh = (__nv_bfloat16*)smraw;   // [256][KST]
    __nv_bfloat16* Ksl = Ksh + 256*KST;
    __nv_bfloat16* Vth = Ksl + 256*KST;           // [32][VST] (d-major, k across)
    __nv_bfloat16* Vtl = Vth + 32*VST;
    float*         b2s = (float*)(Vtl + 32*VST);  // [256]

    const int tid = threadIdx.x, lane = tid & 31, w = tid >> 5;
    const int g = lane >> 2, tg = lane & 3;
    const int h = blockIdx.x, s = blockIdx.y;
    const size_t headBase = ((size_t)s*HH + h) * SS * DD;

    // ---- stage K (coalesced uint4): 1024 uint4 per buffer ----
    {
        const uint4* sh = (const uint4*)(g_Kh + headBase);
        const uint4* sl = (const uint4*)(g_Kl + headBase);
#pragma unroll
        for (int it = 0; it < 4; it++) {
            int i = tid + it*256;
            int row = i >> 2, q4 = i & 3;
            *(uint4*)&Ksh[row*KST + q4*8] = sh[i];
            *(uint4*)&Ksl[row*KST + q4*8] = sl[i];
        }
    }
    // ---- stage V transposed: Vt[d][k], one row per thread ----
    {
        const u32* sh = (const u32*)(g_Vh + headBase + (size_t)tid*DD);
        const u32* sl = (const u32*)(g_Vl + headBase + (size_t)tid*DD);
#pragma unroll
        for (int j = 0; j < 16; j++) {
            int d = 2*j;
            u32 v = sh[j];
            __nv_bfloat162 p = *(__nv_bfloat162*)&v;
            Vth[ d   *VST + tid] = p.x;
            Vth[(d+1)*VST + tid] = p.y;
            v = sl[j];
            p = *(__nv_bfloat162*)&v;
            Vtl[ d   *VST + tid] = p.x;
            Vtl[(d+1)*VST + tid] = p.y;
        }
    }
    b2s[tid] = bias2[(size_t)s*SS + tid];
    __syncthreads();

    // ---- Q fragments: M=32 per warp (mt=0,1), direct from gmem ----
    const int q0 = w * 32;
    u32 qh[2][2][4], ql[2][2][4];
    {
        const u32* srcH = (const u32*)(g_Qh + headBase);
        const u32* srcL = (const u32*)(g_Ql + headBase);
#pragma unroll
        for (int mt = 0; mt < 2; mt++) {
            int r0 = q0 + mt*16 + g, r1 = r0 + 8;
#pragma unroll
            for (int sl2 = 0; sl2 < 2; sl2++) {
                int kc = sl2*8 + tg;
                qh[mt][sl2][0] = srcH[r0*16 + kc];
                qh[mt][sl2][1] = srcH[r1*16 + kc];
                qh[mt][sl2][2] = srcH[r0*16 + kc + 4];
                qh[mt][sl2][3] = srcH[r1*16 + kc + 4];
                ql[mt][sl2][0] = srcL[r0*16 + kc];
                ql[mt][sl2][1] = srcL[r1*16 + kc];
                ql[mt][sl2][2] = srcL[r0*16 + kc + 4];
                ql[mt][sl2][3] = srcL[r1*16 + kc + 4];
            }
        }
    }

    const float* b1a[2];  // row g of mt block
    const float* b1b[2];  // row g+8
#pragma unroll
    for (int mt = 0; mt < 2; mt++) {
        b1a[mt] = bias1 + ((size_t)h*SS + q0 + mt*16 + g) * SS;
        b1b[mt] = b1a[mt] + 8*SS;
    }

    float acc[2][4][4];
#pragma unroll
    for (int mt = 0; mt < 2; mt++)
#pragma unroll
        for (int a = 0; a < 4; a++)
#pragma unroll
            for (int b = 0; b < 4; b++) acc[mt][a][b] = 0.f;
    float m_a[2] = {-1e30f, -1e30f}, m_b[2] = {-1e30f, -1e30f};
    float l_a[2] = {0.f, 0.f},       l_b[2] = {0.f, 0.f};

    // ldmatrix row-address offsets for this lane
    const int kr = lane & 7, kcb = lane >> 3;          // K: row kr in n8 block, k-block kcb*8
    const int vr = lane & 7, vcb = (lane >> 3) & 1;    // V: row vr in d8 block, k-block vcb*8

#pragma unroll
    for (int c4 = 0; c4 < 4; c4++) {
        const int n0c = c4 * 64;
        // ---- QK^T for this 64-key chunk ----
        float sc[2][8][4];
#pragma unroll
        for (int mt = 0; mt < 2; mt++)
#pragma unroll
            for (int nt = 0; nt < 8; nt++)
#pragma unroll
                for (int c = 0; c < 4; c++) sc[mt][nt][c] = 0.f;

#pragma unroll
        for (int nt = 0; nt < 8; nt++) {
            int n8 = n0c + nt*8;
            u32 bh[4], bl[4];
            ldsm4(bh, &Ksh[(n8 + kr)*KST + kcb*8]);
            ldsm4(bl, &Ksl[(n8 + kr)*KST + kcb*8]);
#pragma unroll
            for (int mt = 0; mt < 2; mt++) {
#pragma unroll
                for (int sl2 = 0; sl2 < 2; sl2++) {
                    mma_bf16(sc[mt][nt], qh[mt][sl2], &bh[sl2*2]);
                    mma_bf16(sc[mt][nt], qh[mt][sl2], &bl[sl2*2]);
                    mma_bf16(sc[mt][nt], ql[mt][sl2], &bh[sl2*2]);
                }
            }
        }

        // ---- bias add + per-row max, rescale ----
#pragma unroll
        for (int mt = 0; mt < 2; mt++) {
            float ta = -1e30f, tb = -1e30f;
#pragma unroll
            for (int nt = 0; nt < 8; nt++) {
                int c = n0c + nt*8 + tg*2;
                float2 ba = *(const float2*)(b1a[mt] + c);
                float2 bb = *(const float2*)(b1b[mt] + c);
                float2 b2v = *(float2*)&b2s[c];
                sc[mt][nt][0] += ba.x + b2v.x;
                sc[mt][nt][1] += ba.y + b2v.y;
                sc[mt][nt][2] += bb.x + b2v.x;
                sc[mt][nt][3] += bb.y + b2v.y;
                ta = fmaxf(ta, fmaxf(sc[mt][nt][0], sc[mt][nt][1]));
                tb = fmaxf(tb, fmaxf(sc[mt][nt][2], sc[mt][nt][3]));
            }
            ta = fmaxf(ta, __shfl_xor_sync(0xffffffffu, ta, 1));
            ta = fmaxf(ta, __shfl_xor_sync(0xffffffffu, ta, 2));
            tb = fmaxf(tb, __shfl_xor_sync(0xffffffffu, tb, 1));
            tb = fmaxf(tb, __shfl_xor_sync(0xffffffffu, tb, 2));

            float mna = fmaxf(m_a[mt], ta), mnb = fmaxf(m_b[mt], tb);
            float sca = __expf(m_a[mt] - mna), scb = __expf(m_b[mt] - mnb);
            m_a[mt] = mna; m_b[mt] = mnb;
            l_a[mt] *= sca; l_b[mt] *= scb;
#pragma unroll
            for (int nd = 0; nd < 4; nd++) {
                acc[mt][nd][0] *= sca; acc[mt][nd][1] *= sca;
                acc[mt][nd][2] *= scb; acc[mt][nd][3] *= scb;
            }
        }

        // ---- fused exp + pack + P·V per k16 (4 steps of 16 keys) ----
#pragma unroll
        for (int s8 = 0; s8 < 4; s8++) {
            u32 ah[2][4], al[2][4];
#pragma unroll
            for (int mt = 0; mt < 2; mt++) {
#pragma unroll
                for (int half = 0; half < 2; half++) {
                    int nt = 2*s8 + half;
                    float p0 = __expf(sc[mt][nt][0] - m_a[mt]);
                    float p1 = __expf(sc[mt][nt][1] - m_a[mt]);
                    float p2 = __expf(sc[mt][nt][2] - m_b[mt]);
                    float p3 = __expf(sc[mt][nt][3] - m_b[mt]);
                    l_a[mt] += p0 + p1;
                    l_b[mt] += p2 + p3;
                    __nv_bfloat162 hv, lv;
                    split2(p0, hv.x, lv.x); split2(p1, hv.y, lv.y);
                    ah[mt][half*2]     = *(u32*)&hv;  al[mt][half*2]     = *(u32*)&lv;
                    split2(p2, hv.x, lv.x); split2(p3, hv.y, lv.y);
                    ah[mt][half*2 + 1] = *(u32*)&hv;  al[mt][half*2 + 1] = *(u32*)&lv;
                }
            }
            int kkg = n0c + s8*16;
#pragma unroll
            for (int nd = 0; nd < 4; nd++) {
                u32 vh[2], vl[2];
                ldsm2(vh, &Vth[(nd*8 + vr)*VST + kkg + vcb*8]);
                ldsm2(vl, &Vtl[(nd*8 + vr)*VST + kkg + vcb*8]);
#pragma unroll
                for (int mt = 0; mt < 2; mt++) {
                    mma_bf16(acc[mt][nd], ah[mt], vh);
                    mma_bf16(acc[mt][nd], ah[mt], vl);
                    mma_bf16(acc[mt][nd], al[mt], vh);
                }
            }
        }
    }

    // ---- reduce row-sums across the 4 tg lanes, epilogue per mt ----
#pragma unroll
    for (int mt = 0; mt < 2; mt++) {
        float la = l_a[mt], lb = l_b[mt];
        la += __shfl_xor_sync(0xffffffffu, la, 1);
        la += __shfl_xor_sync(0xffffffffu, la, 2);
        lb += __shfl_xor_sync(0xffffffffu, lb, 1);
        lb += __shfl_xor_sync(0xffffffffu, lb, 2);
        const float inva = 1.0f / la;
        const float invb = 1.0f / lb;
        const int ta_t = s*SS + q0 + mt*16 + g;
        const int tb_t = ta_t + 8;
#pragma unroll
        for (int nd = 0; nd < 4; nd++) {
            int col = h*DD + nd*8 + tg*2;
            float2 ga = *(const float2*)(g_G + (size_t)ta_t*CC + col);
            float2 gb = *(const float2*)(g_G + (size_t)tb_t*CC + col);
            float o0 = acc[mt][nd][0] * inva * ga.x;
            float o1 = acc[mt][nd][1] * inva * ga.y;
            float o2 = acc[mt][nd][2] * invb * gb.x;
            float o3 = acc[mt][nd][3] * invb * gb.y;
            __nv_bfloat162 oh, ol;
            split2(o0, oh.x, ol.x); split2(o1, oh.y, ol.y);
            *(__nv_bfloat162*)&g_Oh[(size_t)ta_t*CC + col] = oh;
            *(__nv_bfloat162*)&g_Ol[(size_t)ta_t*CC + col] = ol;
            split2(o2, oh.x, ol.x); split2(o3, oh.y, ol.y);
            *(__nv_bfloat162*)&g_Oh[(size_t)tb_t*CC + col] = oh;
            *(__nv_bfloat162*)&g_Ol[(size_t)tb_t*CC + col] = ol;
        }
    }
}

// ---------------- launch ----------------
extern "C" void kernel_launch(void* const* d_in, const int* in_sizes, int n_in,
                              void* d_out, int out_size)
{
    const float* q_x   = (const float*)d_in[0];
    const float* kv_x  = (const float*)d_in[1];
    const float* bias1 = (const float*)d_in[2];
    const float* bias2 = (const float*)d_in[3];
    const float* bg    = (const float*)d_in[8];
    const float* bo    = (const float*)d_in[10];
    float* out = (float*)d_out;

    cudaFuncSetAttribute(proj_kernel<0>, cudaFuncAttributeMaxDynamicSharedMemorySize, PROJ_SMEM);
    cudaFuncSetAttribute(proj_kernel<1>, cudaFuncAttributeMaxDynamicSharedMemorySize, PROJ_SMEM);
    cudaFuncSetAttribute(proj_kernel<2>, cudaFuncAttributeMaxDynamicSharedMemorySize, PROJ_SMEM);
    cudaFuncSetAttribute(attn_kernel,    cudaFuncAttributeMaxDynamicSharedMemorySize, ATTN_SMEM);

    prep_w<<<64, 256>>>((const float*)d_in[4], (const float*)d_in[5],
                        (const float*)d_in[6], (const float*)d_in[7],
                        (const float*)d_in[9]);
    proj_kernel<0><<<dim3(512, 2), 256, PROJ_SMEM>>>(q_x,  bg, nullptr);
    proj_kernel<1><<<dim3(512, 2), 256, PROJ_SMEM>>>(kv_x, nullptr, nullptr);
    attn_kernel<<<dim3(HH, SS), 256, ATTN_SMEM>>>(bias1, bias2);
    proj_kernel<2><<<dim3(512, 1), 256, PROJ_SMEM>>>(nullptr, bo, out);
}

// round 7
// speedup vs baseline: 1.1273x; 1.1273x over previous
#include <cuda_runtime.h>
#include <cuda_bf16.h>

#define SS 256
#define CC 128
#define HH 4
#define DD 32
#define TT (SS*SS)

typedef unsigned int u32;

// ---------------- global scratch (no allocations allowed) ----------------
#define NQ (SS*HH*SS*DD)   // 8,388,608
__device__ __nv_bfloat16 g_Qh[NQ], g_Ql[NQ];
__device__ __nv_bfloat16 g_Kh[NQ], g_Kl[NQ];
__device__ __nv_bfloat16 g_Vh[NQ], g_Vl[NQ];
__device__ float         g_G [(size_t)TT*CC];
__device__ __nv_bfloat16 g_Oh[(size_t)TT*CC], g_Ol[(size_t)TT*CC];
__device__ __nv_bfloat16 g_Wqg_h[2*CC*CC], g_Wqg_l[2*CC*CC];
__device__ __nv_bfloat16 g_Wkv_h[2*CC*CC], g_Wkv_l[2*CC*CC];
__device__ __nv_bfloat16 g_Wo_h [CC*CC],   g_Wo_l [CC*CC];

__device__ __forceinline__ void split2(float v, __nv_bfloat16& h, __nv_bfloat16& l) {
    h = __float2bfloat16(v);
    l = __float2bfloat16(v - __bfloat162float(h));
}

__device__ __forceinline__ void mma_bf16(float* d, const u32* a, const u32* b) {
    asm volatile(
      "mma.sync.aligned.m16n8k16.row.col.f32.bf16.bf16.f32 "
      "{%0,%1,%2,%3}, {%4,%5,%6,%7}, {%8,%9}, {%0,%1,%2,%3};\n"
      : "+f"(d[0]), "+f"(d[1]), "+f"(d[2]), "+f"(d[3])
      : "r"(a[0]), "r"(a[1]), "r"(a[2]), "r"(a[3]), "r"(b[0]), "r"(b[1]));
}

__device__ __forceinline__ void ldsm4(u32* r, const void* p) {
    u32 a = (u32)__cvta_generic_to_shared(p);
    asm volatile("ldmatrix.sync.aligned.m8n8.x4.shared.b16 {%0,%1,%2,%3}, [%4];"
                 : "=r"(r[0]), "=r"(r[1]), "=r"(r[2]), "=r"(r[3]) : "r"(a));
}
__device__ __forceinline__ void ldsm2(u32* r, const void* p) {
    u32 a = (u32)__cvta_generic_to_shared(p);
    asm volatile("ldmatrix.sync.aligned.m8n8.x2.shared.b16 {%0,%1}, [%2];"
                 : "=r"(r[0]), "=r"(r[1]) : "r"(a));
}

// ---------------- weight prep: fp32 -> split bf16, stacked ----------------
__global__ void prep_w(const float* __restrict__ wq, const float* __restrict__ wk,
                       const float* __restrict__ wv, const float* __restrict__ wg,
                       const float* __restrict__ wo) {
    int i = blockIdx.x * blockDim.x + threadIdx.x;
    if (i >= CC*CC) return;
    split2(wq[i], g_Wqg_h[i],          g_Wqg_l[i]);
    split2(wg[i], g_Wqg_h[CC*CC + i],  g_Wqg_l[CC*CC + i]);
    split2(wk[i], g_Wkv_h[i],          g_Wkv_l[i]);
    split2(wv[i], g_Wkv_h[CC*CC + i],  g_Wkv_l[CC*CC + i]);
    split2(wo[i], g_Wo_h[i],           g_Wo_l[i]);
}

// ---------------- projection GEMM (bf16 3x-split, mma.sync) ----------------
#define AST 72
#define PROJ_SMEM (4*128*AST*2)

template<int MODE>
__global__ void __launch_bounds__(256, 2) proj_kernel(const float* __restrict__ X,
                                                      const float* __restrict__ bias,
                                                      float* __restrict__ outp)
{
    extern __shared__ __nv_bfloat16 sm[];
    __nv_bfloat16* Ah = sm;
    __nv_bfloat16* Al = sm + 128*AST;
    __nv_bfloat16* Bh = sm + 2*128*AST;
    __nv_bfloat16* Bl = sm + 3*128*AST;

    const int tid = threadIdx.x;
    const int lane = tid & 31;
    const int w = tid >> 5;
    const int g = lane >> 2;
    const int tg = lane & 3;
    const int wm = w & 3;
    const int wn = w >> 2;
    const int m0 = blockIdx.x * 128;
    const int n0 = blockIdx.y * 128;

    const __nv_bfloat16 *Wh, *Wl;
    if (MODE == 0)      { Wh = g_Wqg_h; Wl = g_Wqg_l; }
    else if (MODE == 1) { Wh = g_Wkv_h; Wl = g_Wkv_l; }
    else                { Wh = g_Wo_h;  Wl = g_Wo_l;  }

    float acc[2][8][4];
#pragma unroll
    for (int a = 0; a < 2; a++)
#pragma unroll
        for (int b = 0; b < 8; b++)
#pragma unroll
            for (int c = 0; c < 4; c++) acc[a][b][c] = 0.f;

    for (int ks = 0; ks < 2; ks++) {
        const int kbase = ks * 64;
        if (MODE < 2) {
#pragma unroll
            for (int i = 0; i < 8; i++) {
                int lin = tid + 256*i;
                int r = lin >> 4;
                int c = (lin & 15) * 4;
                float4 xv = *(const float4*)(X + (size_t)(m0+r)*CC + kbase + c);
                split2(xv.x, Ah[r*AST+c+0], Al[r*AST+c+0]);
                split2(xv.y, Ah[r*AST+c+1], Al[r*AST+c+1]);
                split2(xv.z, Ah[r*AST+c+2], Al[r*AST+c+2]);
                split2(xv.w, Ah[r*AST+c+3], Al[r*AST+c+3]);
            }
        } else {
#pragma unroll
            for (int i = 0; i < 16; i++) {
                int lin = tid + 256*i;
                int r = lin >> 5;
                int c = (lin & 31) * 2;
                *(u32*)&Ah[r*AST+c] = *(const u32*)(g_Oh + (size_t)(m0+r)*CC + kbase + c);
                *(u32*)&Al[r*AST+c] = *(const u32*)(g_Ol + (size_t)(m0+r)*CC + kbase + c);
            }
        }
#pragma unroll
        for (int i = 0; i < 16; i++) {
            int lin = tid + 256*i;
            int r = lin >> 5;
            int c = (lin & 31) * 2;
            *(u32*)&Bh[r*AST+c] = *(const u32*)(Wh + (size_t)(n0+r)*CC + kbase + c);
            *(u32*)&Bl[r*AST+c] = *(const u32*)(Wl + (size_t)(n0+r)*CC + kbase + c);
        }
        __syncthreads();

#pragma unroll
        for (int k16 = 0; k16 < 4; k16++) {
            const int kk = k16*16 + tg*2;
            u32 ah[2][4], al[2][4];
#pragma unroll
            for (int mt = 0; mt < 2; mt++) {
                int row = wm*32 + mt*16 + g;
                ah[mt][0] = *(u32*)&Ah[ row   *AST + kk];
                ah[mt][1] = *(u32*)&Ah[(row+8)*AST + kk];
                ah[mt][2] = *(u32*)&Ah[ row   *AST + kk + 8];
                ah[mt][3] = *(u32*)&Ah[(row+8)*AST + kk + 8];
                al[mt][0] = *(u32*)&Al[ row   *AST + kk];
                al[mt][1] = *(u32*)&Al[(row+8)*AST + kk];
                al[mt][2] = *(u32*)&Al[ row   *AST + kk + 8];
                al[mt][3] = *(u32*)&Al[(row+8)*AST + kk + 8];
            }
#pragma unroll
            for (int nt = 0; nt < 8; nt++) {
                int n = wn*64 + nt*8 + g;
                u32 bh[2], bl[2];
                bh[0] = *(u32*)&Bh[n*AST + kk];
                bh[1] = *(u32*)&Bh[n*AST + kk + 8];
                bl[0] = *(u32*)&Bl[n*AST + kk];
                bl[1] = *(u32*)&Bl[n*AST + kk + 8];
#pragma unroll
                for (int mt = 0; mt < 2; mt++) {
                    mma_bf16(acc[mt][nt], ah[mt], bh);
                    mma_bf16(acc[mt][nt], ah[mt], bl);
                    mma_bf16(acc[mt][nt], al[mt], bh);
                }
            }
        }
        __syncthreads();
    }

#pragma unroll
    for (int mt = 0; mt < 2; mt++) {
#pragma unroll
        for (int nt = 0; nt < 8; nt++) {
#pragma unroll
            for (int rr = 0; rr < 2; rr++) {
                int m   = m0 + wm*32 + mt*16 + g + rr*8;
                int col = wn*64 + nt*8 + tg*2;
                float y0 = acc[mt][nt][rr*2+0];
                float y1 = acc[mt][nt][rr*2+1];
                if (MODE == 2) {
                    float2 o; o.x = y0 + bias[col]; o.y = y1 + bias[col+1];
                    *(float2*)(outp + (size_t)m*CC + col) = o;
                } else if (blockIdx.y == 0) {
                    if (MODE == 0) { y0 *= 0.17677669529663687f; y1 *= 0.17677669529663687f; }
                    int hh = col >> 5, d = col & 31;
                    int si = m >> 8,  j = m & 255;
                    size_t idx = (((size_t)si*HH + hh)*SS + j)*DD + d;
                    __nv_bfloat162 vh, vl;
                    split2(y0, vh.x, vl.x);
                    split2(y1, vh.y, vl.y);
                    if (MODE == 0) { *(__nv_bfloat162*)&g_Qh[idx] = vh; *(__nv_bfloat162*)&g_Ql[idx] = vl; }
                    else           { *(__nv_bfloat162*)&g_Kh[idx] = vh; *(__nv_bfloat162*)&g_Kl[idx] = vl; }
                } else {
                    if (MODE == 0) {
                        float s0 = 1.f/(1.f + __expf(-(y0 + bias[col])));
                        float s1 = 1.f/(1.f + __expf(-(y1 + bias[col+1])));
                        *(float2*)(g_G + (size_t)m*CC + col) = make_float2(s0, s1);
                    } else {
                        int hh = col >> 5, d = col & 31;
                        int si = m >> 8,  j = m & 255;
                        size_t idx = (((size_t)si*HH + hh)*SS + j)*DD + d;
                        __nv_bfloat162 vh, vl;
                        split2(y0, vh.x, vl.x);
                        split2(y1, vh.y, vl.y);
                        *(__nv_bfloat162*)&g_Vh[idx] = vh;
                        *(__nv_bfloat162*)&g_Vl[idx] = vl;
                    }
                }
            }
        }
    }
}

// ---------------- attention v4: 8 warps M=32, 32-key chunks, 2 CTAs/SM ----
#define KST 40
#define VST 264
#define ATTN_SMEM (2*256*KST*2 + 2*32*VST*2 + 256*4)   // 75776 B

__global__ void __launch_bounds__(256, 2) attn_kernel(const float* __restrict__ bias1,
                                                      const float* __restrict__ bias2)
{
    extern __shared__ char smraw[];
    __nv_bfloat16* Ksh = (__nv_bfloat16*)smraw;   // [256][KST]
    __nv_bfloat16* Ksl = Ksh + 256*KST;
    __nv_bfloat16* Vth = Ksl + 256*KST;           // [32][VST] (d-major, k across)
    __nv_bfloat16* Vtl = Vth + 32*VST;
    float*         b2s = (float*)(Vtl + 32*VST);  // [256]

    const int tid = threadIdx.x, lane = tid & 31, w = tid >> 5;
    const int g = lane >> 2, tg = lane & 3;
    const int h = blockIdx.x, s = blockIdx.y;
    const size_t headBase = ((size_t)s*HH + h) * SS * DD;

    // ---- stage K (coalesced uint4): 1024 uint4 per buffer ----
    {
        const uint4* sh = (const uint4*)(g_Kh + headBase);
        const uint4* sl = (const uint4*)(g_Kl + headBase);
#pragma unroll
        for (int it = 0; it < 4; it++) {
            int i = tid + it*256;
            int row = i >> 2, q4 = i & 3;
            *(uint4*)&Ksh[row*KST + q4*8] = sh[i];
            *(uint4*)&Ksl[row*KST + q4*8] = sl[i];
        }
    }
    // ---- stage V transposed: Vt[d][k], one row per thread ----
    {
        const u32* sh = (const u32*)(g_Vh + headBase + (size_t)tid*DD);
        const u32* sl = (const u32*)(g_Vl + headBase + (size_t)tid*DD);
#pragma unroll
        for (int j = 0; j < 16; j++) {
            int d = 2*j;
            u32 v = sh[j];
            __nv_bfloat162 p = *(__nv_bfloat162*)&v;
            Vth[ d   *VST + tid] = p.x;
            Vth[(d+1)*VST + tid] = p.y;
            v = sl[j];
            p = *(__nv_bfloat162*)&v;
            Vtl[ d   *VST + tid] = p.x;
            Vtl[(d+1)*VST + tid] = p.y;
        }
    }
    b2s[tid] = bias2[(size_t)s*SS + tid];

    // ---- Q fragments: M=32 per warp (mt=0,1), gmem loads overlap staging ----
    const int q0 = w * 32;
    u32 qh[2][2][4], ql[2][2][4];
    {
        const u32* srcH = (const u32*)(g_Qh + headBase);
        const u32* srcL = (const u32*)(g_Ql + headBase);
#pragma unroll
        for (int mt = 0; mt < 2; mt++) {
            int r0 = q0 + mt*16 + g, r1 = r0 + 8;
#pragma unroll
            for (int sl2 = 0; sl2 < 2; sl2++) {
                int kc = sl2*8 + tg;
                qh[mt][sl2][0] = srcH[r0*16 + kc];
                qh[mt][sl2][1] = srcH[r1*16 + kc];
                qh[mt][sl2][2] = srcH[r0*16 + kc + 4];
                qh[mt][sl2][3] = srcH[r1*16 + kc + 4];
                ql[mt][sl2][0] = srcL[r0*16 + kc];
                ql[mt][sl2][1] = srcL[r1*16 + kc];
                ql[mt][sl2][2] = srcL[r0*16 + kc + 4];
                ql[mt][sl2][3] = srcL[r1*16 + kc + 4];
            }
        }
    }
    __syncthreads();

    float acc[2][4][4];
#pragma unroll
    for (int mt = 0; mt < 2; mt++)
#pragma unroll
        for (int a = 0; a < 4; a++)
#pragma unroll
            for (int b = 0; b < 4; b++) acc[mt][a][b] = 0.f;
    float m_a[2] = {-1e30f, -1e30f}, m_b[2] = {-1e30f, -1e30f};
    float l_a[2] = {0.f, 0.f},       l_b[2] = {0.f, 0.f};

    const int kr = lane & 7, kcb = lane >> 3;          // K ldsm4 addressing
    const int vr = lane & 7, vcb = (lane >> 3) & 1;    // V ldsm2 addressing

#pragma unroll
    for (int c4 = 0; c4 < 8; c4++) {                   // 8 chunks of 32 keys
        const int n0c = c4 * 32;
        // ---- QK^T for this 32-key chunk ----
        float sc[2][4][4];
#pragma unroll
        for (int mt = 0; mt < 2; mt++)
#pragma unroll
            for (int nt = 0; nt < 4; nt++)
#pragma unroll
                for (int c = 0; c < 4; c++) sc[mt][nt][c] = 0.f;

#pragma unroll
        for (int nt = 0; nt < 4; nt++) {
            int n8 = n0c + nt*8;
            u32 bh[4], bl[4];
            ldsm4(bh, &Ksh[(n8 + kr)*KST + kcb*8]);
            ldsm4(bl, &Ksl[(n8 + kr)*KST + kcb*8]);
#pragma unroll
            for (int mt = 0; mt < 2; mt++) {
#pragma unroll
                for (int sl2 = 0; sl2 < 2; sl2++) {
                    mma_bf16(sc[mt][nt], qh[mt][sl2], &bh[sl2*2]);
                    mma_bf16(sc[mt][nt], qh[mt][sl2], &bl[sl2*2]);
                    mma_bf16(sc[mt][nt], ql[mt][sl2], &bh[sl2*2]);
                }
            }
        }

        // ---- bias add + per-row max, rescale ----
#pragma unroll
        for (int mt = 0; mt < 2; mt++) {
            const float* b1a = bias1 + ((size_t)h*SS + q0 + mt*16 + g) * SS;
            const float* b1b = b1a + 8*SS;
            float ta = -1e30f, tb = -1e30f;
#pragma unroll
            for (int nt = 0; nt < 4; nt++) {
                int c = n0c + nt*8 + tg*2;
                float2 ba = *(const float2*)(b1a + c);
                float2 bb = *(const float2*)(b1b + c);
                float2 b2v = *(float2*)&b2s[c];
                sc[mt][nt][0] += ba.x + b2v.x;
                sc[mt][nt][1] += ba.y + b2v.y;
                sc[mt][nt][2] += bb.x + b2v.x;
                sc[mt][nt][3] += bb.y + b2v.y;
                ta = fmaxf(ta, fmaxf(sc[mt][nt][0], sc[mt][nt][1]));
                tb = fmaxf(tb, fmaxf(sc[mt][nt][2], sc[mt][nt][3]));
            }
            ta = fmaxf(ta, __shfl_xor_sync(0xffffffffu, ta, 1));
            ta = fmaxf(ta, __shfl_xor_sync(0xffffffffu, ta, 2));
            tb = fmaxf(tb, __shfl_xor_sync(0xffffffffu, tb, 1));
            tb = fmaxf(tb, __shfl_xor_sync(0xffffffffu, tb, 2));

            float mna = fmaxf(m_a[mt], ta), mnb = fmaxf(m_b[mt], tb);
            float sca = __expf(m_a[mt] - mna), scb = __expf(m_b[mt] - mnb);
            m_a[mt] = mna; m_b[mt] = mnb;
            l_a[mt] *= sca; l_b[mt] *= scb;
#pragma unroll
            for (int nd = 0; nd < 4; nd++) {
                acc[mt][nd][0] *= sca; acc[mt][nd][1] *= sca;
                acc[mt][nd][2] *= scb; acc[mt][nd][3] *= scb;
            }
        }

        // ---- fused exp + pack + P·V per k16 (2 steps of 16 keys) ----
#pragma unroll
        for (int s8 = 0; s8 < 2; s8++) {
            u32 ah[2][4], al[2][4];
#pragma unroll
            for (int mt = 0; mt < 2; mt++) {
#pragma unroll
                for (int half = 0; half < 2; half++) {
                    int nt = 2*s8 + half;
                    float p0 = __expf(sc[mt][nt][0] - m_a[mt]);
                    float p1 = __expf(sc[mt][nt][1] - m_a[mt]);
                    float p2 = __expf(sc[mt][nt][2] - m_b[mt]);
                    float p3 = __expf(sc[mt][nt][3] - m_b[mt]);
                    l_a[mt] += p0 + p1;
                    l_b[mt] += p2 + p3;
                    __nv_bfloat162 hv, lv;
                    split2(p0, hv.x, lv.x); split2(p1, hv.y, lv.y);
                    ah[mt][half*2]     = *(u32*)&hv;  al[mt][half*2]     = *(u32*)&lv;
                    split2(p2, hv.x, lv.x); split2(p3, hv.y, lv.y);
                    ah[mt][half*2 + 1] = *(u32*)&hv;  al[mt][half*2 + 1] = *(u32*)&lv;
                }
            }
            int kkg = n0c + s8*16;
#pragma unroll
            for (int nd = 0; nd < 4; nd++) {
                u32 vh[2], vl[2];
                ldsm2(vh, &Vth[(nd*8 + vr)*VST + kkg + vcb*8]);
                ldsm2(vl, &Vtl[(nd*8 + vr)*VST + kkg + vcb*8]);
#pragma unroll
                for (int mt = 0; mt < 2; mt++) {
                    mma_bf16(acc[mt][nd], ah[mt], vh);
                    mma_bf16(acc[mt][nd], ah[mt], vl);
                    mma_bf16(acc[mt][nd], al[mt], vh);
                }
            }
        }
    }

    // ---- reduce row-sums across the 4 tg lanes, epilogue per mt ----
#pragma unroll
    for (int mt = 0; mt < 2; mt++) {
        float la = l_a[mt], lb = l_b[mt];
        la += __shfl_xor_sync(0xffffffffu, la, 1);
        la += __shfl_xor_sync(0xffffffffu, la, 2);
        lb += __shfl_xor_sync(0xffffffffu, lb, 1);
        lb += __shfl_xor_sync(0xffffffffu, lb, 2);
        const float inva = 1.0f / la;
        const float invb = 1.0f / lb;
        const int ta_t = s*SS + q0 + mt*16 + g;
        const int tb_t = ta_t + 8;
#pragma unroll
        for (int nd = 0; nd < 4; nd++) {
            int col = h*DD + nd*8 + tg*2;
            float2 ga = *(const float2*)(g_G + (size_t)ta_t*CC + col);
            float2 gb = *(const float2*)(g_G + (size_t)tb_t*CC + col);
            float o0 = acc[mt][nd][0] * inva * ga.x;
            float o1 = acc[mt][nd][1] * inva * ga.y;
            float o2 = acc[mt][nd][2] * invb * gb.x;
            float o3 = acc[mt][nd][3] * invb * gb.y;
            __nv_bfloat162 oh, ol;
            split2(o0, oh.x, ol.x); split2(o1, oh.y, ol.y);
            *(__nv_bfloat162*)&g_Oh[(size_t)ta_t*CC + col] = oh;
            *(__nv_bfloat162*)&g_Ol[(size_t)ta_t*CC + col] = ol;
            split2(o2, oh.x, ol.x); split2(o3, oh.y, ol.y);
            *(__nv_bfloat162*)&g_Oh[(size_t)tb_t*CC + col] = oh;
            *(__nv_bfloat162*)&g_Ol[(size_t)tb_t*CC + col] = ol;
        }
    }
}

// ---------------- launch ----------------
extern "C" void kernel_launch(void* const* d_in, const int* in_sizes, int n_in,
                              void* d_out, int out_size)
{
    const float* q_x   = (const float*)d_in[0];
    const float* kv_x  = (const float*)d_in[1];
    const float* bias1 = (const float*)d_in[2];
    const float* bias2 = (const float*)d_in[3];
    const float* bg    = (const float*)d_in[8];
    const float* bo    = (const float*)d_in[10];
    float* out = (float*)d_out;

    cudaFuncSetAttribute(proj_kernel<0>, cudaFuncAttributeMaxDynamicSharedMemorySize, PROJ_SMEM);
    cudaFuncSetAttribute(proj_kernel<1>, cudaFuncAttributeMaxDynamicSharedMemorySize, PROJ_SMEM);
    cudaFuncSetAttribute(proj_kernel<2>, cudaFuncAttributeMaxDynamicSharedMemorySize, PROJ_SMEM);
    cudaFuncSetAttribute(attn_kernel,    cudaFuncAttributeMaxDynamicSharedMemorySize, ATTN_SMEM);

    prep_w<<<64, 256>>>((const float*)d_in[4], (const float*)d_in[5],
                        (const float*)d_in[6], (const float*)d_in[7],
                        (const float*)d_in[9]);
    proj_kernel<0><<<dim3(512, 2), 256, PROJ_SMEM>>>(q_x,  bg, nullptr);
    proj_kernel<1><<<dim3(512, 2), 256, PROJ_SMEM>>>(kv_x, nullptr, nullptr);
    attn_kernel<<<dim3(HH, SS), 256, ATTN_SMEM>>>(bias1, bias2);
    proj_kernel<2><<<dim3(512, 1), 256, PROJ_SMEM>>>(nullptr, bo, out);
}

// round 10
// speedup vs baseline: 1.3617x; 1.2080x over previous
#include <cuda_runtime.h>
#include <cuda_fp16.h>

#define SS 256
#define CC 128
#define HH 4
#define DD 32
#define TT (SS*SS)

typedef unsigned int u32;

// ---------------- global scratch (no allocations allowed) ----------------
#define NQ (SS*HH*SS*DD)   // 8,388,608
__device__ __half g_Qh[NQ], g_Ql[NQ];          // Q split (A operand of QK^T)
__device__ __half g_K [NQ];                    // K single fp16
__device__ __half g_V [NQ];                    // V single fp16
__device__ float  g_G [(size_t)TT*CC];
__device__ __half g_O [(size_t)TT*CC];         // attn output single fp16
__device__ __half g_Wqg_h[2*CC*CC], g_Wqg_l[2*CC*CC];   // weights split
__device__ __half g_Wkv_h[2*CC*CC], g_Wkv_l[2*CC*CC];
__device__ __half g_Wo_h [CC*CC],   g_Wo_l [CC*CC];

__device__ __forceinline__ void split2h(float v, __half& h, __half& l) {
    h = __float2half_rn(v);
    l = __float2half_rn(v - __half2float(h));
}

__device__ __forceinline__ void mma_f16(float* d, const u32* a, const u32* b) {
    asm volatile(
      "mma.sync.aligned.m16n8k16.row.col.f32.f16.f16.f32 "
      "{%0,%1,%2,%3}, {%4,%5,%6,%7}, {%8,%9}, {%0,%1,%2,%3};\n"
      : "+f"(d[0]), "+f"(d[1]), "+f"(d[2]), "+f"(d[3])
      : "r"(a[0]), "r"(a[1]), "r"(a[2]), "r"(a[3]), "r"(b[0]), "r"(b[1]));
}

__device__ __forceinline__ void ldsm4(u32* r, const void* p) {
    u32 a = (u32)__cvta_generic_to_shared(p);
    asm volatile("ldmatrix.sync.aligned.m8n8.x4.shared.b16 {%0,%1,%2,%3}, [%4];"
                 : "=r"(r[0]), "=r"(r[1]), "=r"(r[2]), "=r"(r[3]) : "r"(a));
}
__device__ __forceinline__ void ldsm2(u32* r, const void* p) {
    u32 a = (u32)__cvta_generic_to_shared(p);
    asm volatile("ldmatrix.sync.aligned.m8n8.x2.shared.b16 {%0,%1}, [%2];"
                 : "=r"(r[0]), "=r"(r[1]) : "r"(a));
}

// ---------------- weight prep: fp32 -> split fp16, stacked ----------------
__global__ void prep_w(const float* __restrict__ wq, const float* __restrict__ wk,
                       const float* __restrict__ wv, const float* __restrict__ wg,
                       const float* __restrict__ wo) {
    int i = blockIdx.x * blockDim.x + threadIdx.x;
    if (i >= CC*CC) return;
    split2h(wq[i], g_Wqg_h[i],         g_Wqg_l[i]);
    split2h(wg[i], g_Wqg_h[CC*CC + i], g_Wqg_l[CC*CC + i]);
    split2h(wk[i], g_Wkv_h[i],         g_Wkv_l[i]);
    split2h(wv[i], g_Wkv_h[CC*CC + i], g_Wkv_l[CC*CC + i]);
    split2h(wo[i], g_Wo_h[i],          g_Wo_l[i]);
}

// ---------------- projection GEMM (fp16 2-term: A single, W split) ----------
// MODE 0: X=q_x,  W=[Wq;Wg]: by0 -> Q split head layout (scaled), by1 -> sigmoid gate
// MODE 1: X=kv_x, W=[Wk;Wv]: by0 -> K single head layout, by1 -> V single
// MODE 2: A=g_O (fp16), W=Wo: out = y + bo (fp32)
#define AST 72
#define PROJ_SMEM (3*128*AST*2)   // A single + B hi + B lo = 55296 B

template<int MODE>
__global__ void __launch_bounds__(256, 2) proj_kernel(const float* __restrict__ X,
                                                      const float* __restrict__ bias,
                                                      float* __restrict__ outp)
{
    extern __shared__ __half sm[];
    __half* As = sm;
    __half* Bh = sm + 128*AST;
    __half* Bl = sm + 2*128*AST;

    const int tid = threadIdx.x;
    const int lane = tid & 31;
    const int w = tid >> 5;
    const int g = lane >> 2;
    const int tg = lane & 3;
    const int wm = w & 3;
    const int wn = w >> 2;
    const int m0 = blockIdx.x * 128;
    const int n0 = blockIdx.y * 128;

    const __half *Wh, *Wl;
    if (MODE == 0)      { Wh = g_Wqg_h; Wl = g_Wqg_l; }
    else if (MODE == 1) { Wh = g_Wkv_h; Wl = g_Wkv_l; }
    else                { Wh = g_Wo_h;  Wl = g_Wo_l;  }

    float acc[2][8][4];
#pragma unroll
    for (int a = 0; a < 2; a++)
#pragma unroll
        for (int b = 0; b < 8; b++)
#pragma unroll
            for (int c = 0; c < 4; c++) acc[a][b][c] = 0.f;

    for (int ks = 0; ks < 2; ks++) {
        const int kbase = ks * 64;
        // --- stage A (single fp16) ---
        if (MODE < 2) {
#pragma unroll
            for (int i = 0; i < 8; i++) {
                int lin = tid + 256*i;            // float4 units
                int r = lin >> 4;
                int c = (lin & 15) * 4;
                float4 xv = *(const float4*)(X + (size_t)(m0+r)*CC + kbase + c);
                __half2 p01 = __floats2half2_rn(xv.x, xv.y);
                __half2 p23 = __floats2half2_rn(xv.z, xv.w);
                *(u32*)&As[r*AST+c]   = *(u32*)&p01;
                *(u32*)&As[r*AST+c+2] = *(u32*)&p23;
            }
        } else {
#pragma unroll
            for (int i = 0; i < 16; i++) {
                int lin = tid + 256*i;            // u32 units
                int r = lin >> 5;
                int c = (lin & 31) * 2;
                *(u32*)&As[r*AST+c] = *(const u32*)(g_O + (size_t)(m0+r)*CC + kbase + c);
            }
        }
        // --- stage B (weights split, [n][k] row-major) ---
#pragma unroll
        for (int i = 0; i < 16; i++) {
            int lin = tid + 256*i;
            int r = lin >> 5;
            int c = (lin & 31) * 2;
            *(u32*)&Bh[r*AST+c] = *(const u32*)(Wh + (size_t)(n0+r)*CC + kbase + c);
            *(u32*)&Bl[r*AST+c] = *(const u32*)(Wl + (size_t)(n0+r)*CC + kbase + c);
        }
        __syncthreads();

#pragma unroll
        for (int k16 = 0; k16 < 4; k16++) {
            const int kk = k16*16 + tg*2;
            u32 a[2][4];
#pragma unroll
            for (int mt = 0; mt < 2; mt++) {
                int row = wm*32 + mt*16 + g;
                a[mt][0] = *(u32*)&As[ row   *AST + kk];
                a[mt][1] = *(u32*)&As[(row+8)*AST + kk];
                a[mt][2] = *(u32*)&As[ row   *AST + kk + 8];
                a[mt][3] = *(u32*)&As[(row+8)*AST + kk + 8];
            }
#pragma unroll
            for (int nt = 0; nt < 8; nt++) {
                int n = wn*64 + nt*8 + g;
                u32 bh[2], bl[2];
                bh[0] = *(u32*)&Bh[n*AST + kk];
                bh[1] = *(u32*)&Bh[n*AST + kk + 8];
                bl[0] = *(u32*)&Bl[n*AST + kk];
                bl[1] = *(u32*)&Bl[n*AST + kk + 8];
#pragma unroll
                for (int mt = 0; mt < 2; mt++) {
                    mma_f16(acc[mt][nt], a[mt], bh);
                    mma_f16(acc[mt][nt], a[mt], bl);
                }
            }
        }
        __syncthreads();
    }

    // --- epilogue ---
#pragma unroll
    for (int mt = 0; mt < 2; mt++) {
#pragma unroll
        for (int nt = 0; nt < 8; nt++) {
#pragma unroll
            for (int rr = 0; rr < 2; rr++) {
                int m   = m0 + wm*32 + mt*16 + g + rr*8;
                int col = wn*64 + nt*8 + tg*2;
                float y0 = acc[mt][nt][rr*2+0];
                float y1 = acc[mt][nt][rr*2+1];
                if (MODE == 2) {
                    float2 o; o.x = y0 + bias[col]; o.y = y1 + bias[col+1];
                    *(float2*)(outp + (size_t)m*CC + col) = o;
                } else if (blockIdx.y == 0) {
                    // Q (split) or K (single), head layout
                    int hh = col >> 5, d = col & 31;
                    int si = m >> 8,  j = m & 255;
                    size_t idx = (((size_t)si*HH + hh)*SS + j)*DD + d;
                    if (MODE == 0) {
                        y0 *= 0.17677669529663687f; y1 *= 0.17677669529663687f;
                        __half2 vh, vl;
                        split2h(y0, vh.x, vl.x);
                        split2h(y1, vh.y, vl.y);
                        *(__half2*)&g_Qh[idx] = vh;
                        *(__half2*)&g_Ql[idx] = vl;
                    } else {
                        *(__half2*)&g_K[idx] = __floats2half2_rn(y0, y1);
                    }
                } else {
                    if (MODE == 0) {
                        float s0 = 1.f/(1.f + __expf(-(y0 + bias[col])));
                        float s1 = 1.f/(1.f + __expf(-(y1 + bias[col+1])));
                        *(float2*)(g_G + (size_t)m*CC + col) = make_float2(s0, s1);
                    } else {
                        int hh = col >> 5, d = col & 31;
                        int si = m >> 8,  j = m & 255;
                        size_t idx = (((size_t)si*HH + hh)*SS + j)*DD + d;
                        *(__half2*)&g_V[idx] = __floats2half2_rn(y0, y1);
                    }
                }
            }
        }
    }
}

// ---------------- attention v5: fp16 2-term, single K/V buffers ----------
// CTA = one (s,h): 256 threads / 8 warps; warp owns 32 q-rows x all 256 keys.
#define KST 40
#define VST 264
#define ATTN_SMEM (256*KST*2 + 32*VST*2 + 256*4)   // 38400 B

__global__ void __launch_bounds__(256, 2) attn_kernel(const float* __restrict__ bias1,
                                                      const float* __restrict__ bias2)
{
    extern __shared__ char smraw[];
    __half* Ksh = (__half*)smraw;                 // [256][KST]
    __half* Vth = Ksh + 256*KST;                  // [32][VST] (d-major, k across)
    float*  b2s = (float*)(Vth + 32*VST);         // [256]

    const int tid = threadIdx.x, lane = tid & 31, w = tid >> 5;
    const int g = lane >> 2, tg = lane & 3;
    const int h = blockIdx.x, s = blockIdx.y;
    const size_t headBase = ((size_t)s*HH + h) * SS * DD;

    // ---- stage K (coalesced uint4): 1024 uint4 ----
    {
        const uint4* sh = (const uint4*)(g_K + headBase);
#pragma unroll
        for (int it = 0; it < 4; it++) {
            int i = tid + it*256;
            int row = i >> 2, q4 = i & 3;
            *(uint4*)&Ksh[row*KST + q4*8] = sh[i];
        }
    }
    // ---- stage V transposed: Vt[d][k], one row per thread ----
    {
        const u32* sh = (const u32*)(g_V + headBase + (size_t)tid*DD);
#pragma unroll
        for (int j = 0; j < 16; j++) {
            int d = 2*j;
            u32 v = sh[j];
            __half2 p = *(__half2*)&v;
            Vth[ d   *VST + tid] = p.x;
            Vth[(d+1)*VST + tid] = p.y;
        }
    }
    b2s[tid] = bias2[(size_t)s*SS + tid];

    // ---- Q fragments (split), overlap staging ----
    const int q0 = w * 32;
    u32 qh[2][2][4], ql[2][2][4];
    {
        const u32* srcH = (const u32*)(g_Qh + headBase);
        const u32* srcL = (const u32*)(g_Ql + headBase);
#pragma unroll
        for (int mt = 0; mt < 2; mt++) {
            int r0 = q0 + mt*16 + g, r1 = r0 + 8;
#pragma unroll
            for (int sl2 = 0; sl2 < 2; sl2++) {
                int kc = sl2*8 + tg;
                qh[mt][sl2][0] = srcH[r0*16 + kc];
                qh[mt][sl2][1] = srcH[r1*16 + kc];
                qh[mt][sl2][2] = srcH[r0*16 + kc + 4];
                qh[mt][sl2][3] = srcH[r1*16 + kc + 4];
                ql[mt][sl2][0] = srcL[r0*16 + kc];
                ql[mt][sl2][1] = srcL[r1*16 + kc];
                ql[mt][sl2][2] = srcL[r0*16 + kc + 4];
                ql[mt][sl2][3] = srcL[r1*16 + kc + 4];
            }
        }
    }
    __syncthreads();

    float acc[2][4][4];
#pragma unroll
    for (int mt = 0; mt < 2; mt++)
#pragma unroll
        for (int a = 0; a < 4; a++)
#pragma unroll
            for (int b = 0; b < 4; b++) acc[mt][a][b] = 0.f;
    float m_a[2] = {-1e30f, -1e30f}, m_b[2] = {-1e30f, -1e30f};
    float l_a[2] = {0.f, 0.f},       l_b[2] = {0.f, 0.f};

    const int kr = lane & 7, kcb = lane >> 3;
    const int vr = lane & 7, vcb = (lane >> 3) & 1;

#pragma unroll
    for (int c4 = 0; c4 < 8; c4++) {                   // 8 chunks of 32 keys
        const int n0c = c4 * 32;
        // ---- QK^T ----
        float sc[2][4][4];
#pragma unroll
        for (int mt = 0; mt < 2; mt++)
#pragma unroll
            for (int nt = 0; nt < 4; nt++)
#pragma unroll
                for (int c = 0; c < 4; c++) sc[mt][nt][c] = 0.f;

#pragma unroll
        for (int nt = 0; nt < 4; nt++) {
            int n8 = n0c + nt*8;
            u32 kb[4];
            ldsm4(kb, &Ksh[(n8 + kr)*KST + kcb*8]);
#pragma unroll
            for (int mt = 0; mt < 2; mt++) {
#pragma unroll
                for (int sl2 = 0; sl2 < 2; sl2++) {
                    mma_f16(sc[mt][nt], qh[mt][sl2], &kb[sl2*2]);
                    mma_f16(sc[mt][nt], ql[mt][sl2], &kb[sl2*2]);
                }
            }
        }

        // ---- bias add + per-row max, rescale ----
#pragma unroll
        for (int mt = 0; mt < 2; mt++) {
            const float* b1a = bias1 + ((size_t)h*SS + q0 + mt*16 + g) * SS;
            const float* b1b = b1a + 8*SS;
            float ta = -1e30f, tb = -1e30f;
#pragma unroll
            for (int nt = 0; nt < 4; nt++) {
                int c = n0c + nt*8 + tg*2;
                float2 ba = *(const float2*)(b1a + c);
                float2 bb = *(const float2*)(b1b + c);
                float2 b2v = *(float2*)&b2s[c];
                sc[mt][nt][0] += ba.x + b2v.x;
                sc[mt][nt][1] += ba.y + b2v.y;
                sc[mt][nt][2] += bb.x + b2v.x;
                sc[mt][nt][3] += bb.y + b2v.y;
                ta = fmaxf(ta, fmaxf(sc[mt][nt][0], sc[mt][nt][1]));
                tb = fmaxf(tb, fmaxf(sc[mt][nt][2], sc[mt][nt][3]));
            }
            ta = fmaxf(ta, __shfl_xor_sync(0xffffffffu, ta, 1));
            ta = fmaxf(ta, __shfl_xor_sync(0xffffffffu, ta, 2));
            tb = fmaxf(tb, __shfl_xor_sync(0xffffffffu, tb, 1));
            tb = fmaxf(tb, __shfl_xor_sync(0xffffffffu, tb, 2));

            float mna = fmaxf(m_a[mt], ta), mnb = fmaxf(m_b[mt], tb);
            float sca = __expf(m_a[mt] - mna), scb = __expf(m_b[mt] - mnb);
            m_a[mt] = mna; m_b[mt] = mnb;
            l_a[mt] *= sca; l_b[mt] *= scb;
#pragma unroll
            for (int nd = 0; nd < 4; nd++) {
                acc[mt][nd][0] *= sca; acc[mt][nd][1] *= sca;
                acc[mt][nd][2] *= scb; acc[mt][nd][3] *= scb;
            }
        }

        // ---- fused exp + split-fp16 pack + P·V per k16 ----
#pragma unroll
        for (int s8 = 0; s8 < 2; s8++) {
            u32 ah[2][4], al[2][4];
#pragma unroll
            for (int mt = 0; mt < 2; mt++) {
#pragma unroll
                for (int half = 0; half < 2; half++) {
                    int nt = 2*s8 + half;
                    float p0 = __expf(sc[mt][nt][0] - m_a[mt]);
                    float p1 = __expf(sc[mt][nt][1] - m_a[mt]);
                    float p2 = __expf(sc[mt][nt][2] - m_b[mt]);
                    float p3 = __expf(sc[mt][nt][3] - m_b[mt]);
                    l_a[mt] += p0 + p1;
                    l_b[mt] += p2 + p3;
                    __half2 hv, lv;
                    split2h(p0, hv.x, lv.x); split2h(p1, hv.y, lv.y);
                    ah[mt][half*2]     = *(u32*)&hv;  al[mt][half*2]     = *(u32*)&lv;
                    split2h(p2, hv.x, lv.x); split2h(p3, hv.y, lv.y);
                    ah[mt][half*2 + 1] = *(u32*)&hv;  al[mt][half*2 + 1] = *(u32*)&lv;
                }
            }
            int kkg = n0c + s8*16;
#pragma unroll
            for (int nd = 0; nd < 4; nd++) {
                u32 vb[2];
                ldsm2(vb, &Vth[(nd*8 + vr)*VST + kkg + vcb*8]);
#pragma unroll
                for (int mt = 0; mt < 2; mt++) {
                    mma_f16(acc[mt][nd], ah[mt], vb);
                    mma_f16(acc[mt][nd], al[mt], vb);
                }
            }
        }
    }

    // ---- reduce row-sums, epilogue: normalize, gate, fp16 store ----
#pragma unroll
    for (int mt = 0; mt < 2; mt++) {
        float la = l_a[mt], lb = l_b[mt];
        la += __shfl_xor_sync(0xffffffffu, la, 1);
        la += __shfl_xor_sync(0xffffffffu, la, 2);
        lb += __shfl_xor_sync(0xffffffffu, lb, 1);
        lb += __shfl_xor_sync(0xffffffffu, lb, 2);
        const float inva = 1.0f / la;
        const float invb = 1.0f / lb;
        const int ta_t = s*SS + q0 + mt*16 + g;
        const int tb_t = ta_t + 8;
#pragma unroll
        for (int nd = 0; nd < 4; nd++) {
            int col = h*DD + nd*8 + tg*2;
            float2 ga = *(const float2*)(g_G + (size_t)ta_t*CC + col);
            float2 gb = *(const float2*)(g_G + (size_t)tb_t*CC + col);
            float o0 = acc[mt][nd][0] * inva * ga.x;
            float o1 = acc[mt][nd][1] * inva * ga.y;
            float o2 = acc[mt][nd][2] * invb * gb.x;
            float o3 = acc[mt][nd][3] * invb * gb.y;
            *(__half2*)&g_O[(size_t)ta_t*CC + col] = __floats2half2_rn(o0, o1);
            *(__half2*)&g_O[(size_t)tb_t*CC + col] = __floats2half2_rn(o2, o3);
        }
    }
}

// ---------------- launch ----------------
extern "C" void kernel_launch(void* const* d_in, const int* in_sizes, int n_in,
                              void* d_out, int out_size)
{
    const float* q_x   = (const float*)d_in[0];
    const float* kv_x  = (const float*)d_in[1];
    const float* bias1 = (const float*)d_in[2];
    const float* bias2 = (const float*)d_in[3];
    const float* bg    = (const float*)d_in[8];
    const float* bo    = (const float*)d_in[10];
    float* out = (float*)d_out;

    cudaFuncSetAttribute(proj_kernel<0>, cudaFuncAttributeMaxDynamicSharedMemorySize, PROJ_SMEM);
    cudaFuncSetAttribute(proj_kernel<1>, cudaFuncAttributeMaxDynamicSharedMemorySize, PROJ_SMEM);
    cudaFuncSetAttribute(proj_kernel<2>, cudaFuncAttributeMaxDynamicSharedMemorySize, PROJ_SMEM);
    cudaFuncSetAttribute(attn_kernel,    cudaFuncAttributeMaxDynamicSharedMemorySize, ATTN_SMEM);

    prep_w<<<64, 256>>>((const float*)d_in[4], (const float*)d_in[5],
                        (const float*)d_in[6], (const float*)d_in[7],
                        (const float*)d_in[9]);
    proj_kernel<0><<<dim3(512, 2), 256, PROJ_SMEM>>>(q_x,  bg, nullptr);
    proj_kernel<1><<<dim3(512, 2), 256, PROJ_SMEM>>>(kv_x, nullptr, nullptr);
    attn_kernel<<<dim3(HH, SS), 256, ATTN_SMEM>>>(bias1, bias2);
    proj_kernel<2><<<dim3(512, 1), 256, PROJ_SMEM>>>(nullptr, bo, out);
}

// round 12
// speedup vs baseline: 1.4838x; 1.0896x over previous
#include <cuda_runtime.h>
#include <cuda_fp16.h>

#define SS 256
#define CC 128
#define HH 4
#define DD 32
#define TT (SS*SS)

typedef unsigned int u32;

// ---------------- global scratch (no allocations allowed) ----------------
#define NQ (SS*HH*SS*DD)   // 8,388,608
__device__ __half g_Qh[NQ], g_Ql[NQ];          // Q split (A operand of QK^T)
__device__ __half g_K [NQ];                    // K single fp16
__device__ __half g_V [NQ];                    // V single fp16
__device__ float  g_G [(size_t)TT*CC];
__device__ __half g_O [(size_t)TT*CC];         // attn output single fp16
__device__ __half g_Wqg_h[2*CC*CC], g_Wqg_l[2*CC*CC];   // weights split
__device__ __half g_Wkv_h[2*CC*CC], g_Wkv_l[2*CC*CC];
__device__ __half g_Wo_h [CC*CC],   g_Wo_l [CC*CC];
// fragment-ordered bias1 permutation: [h][w][c4][i][lane][4]
__device__ float  g_pb1[4*8*8*8*32*4];         // 1 MB

__device__ __forceinline__ void split2h(float v, __half& h, __half& l) {
    h = __float2half_rn(v);
    l = __float2half_rn(v - __half2float(h));
}

__device__ __forceinline__ void mma_f16(float* d, const u32* a, const u32* b) {
    asm volatile(
      "mma.sync.aligned.m16n8k16.row.col.f32.f16.f16.f32 "
      "{%0,%1,%2,%3}, {%4,%5,%6,%7}, {%8,%9}, {%0,%1,%2,%3};\n"
      : "+f"(d[0]), "+f"(d[1]), "+f"(d[2]), "+f"(d[3])
      : "r"(a[0]), "r"(a[1]), "r"(a[2]), "r"(a[3]), "r"(b[0]), "r"(b[1]));
}

__device__ __forceinline__ void ldsm4(u32* r, const void* p) {
    u32 a = (u32)__cvta_generic_to_shared(p);
    asm volatile("ldmatrix.sync.aligned.m8n8.x4.shared.b16 {%0,%1,%2,%3}, [%4];"
                 : "=r"(r[0]), "=r"(r[1]), "=r"(r[2]), "=r"(r[3]) : "r"(a));
}
__device__ __forceinline__ void ldsm2(u32* r, const void* p) {
    u32 a = (u32)__cvta_generic_to_shared(p);
    asm volatile("ldmatrix.sync.aligned.m8n8.x2.shared.b16 {%0,%1}, [%2];"
                 : "=r"(r[0]), "=r"(r[1]) : "r"(a));
}

// ---------------- weight prep: fp32 -> split fp16, stacked ----------------
__global__ void prep_w(const float* __restrict__ wq, const float* __restrict__ wk,
                       const float* __restrict__ wv, const float* __restrict__ wg,
                       const float* __restrict__ wo) {
    int i = blockIdx.x * blockDim.x + threadIdx.x;
    if (i >= CC*CC) return;
    split2h(wq[i], g_Wqg_h[i],         g_Wqg_l[i]);
    split2h(wg[i], g_Wqg_h[CC*CC + i], g_Wqg_l[CC*CC + i]);
    split2h(wk[i], g_Wkv_h[i],         g_Wkv_l[i]);
    split2h(wv[i], g_Wkv_h[CC*CC + i], g_Wkv_l[CC*CC + i]);
    split2h(wo[i], g_Wo_h[i],          g_Wo_l[i]);
}

// ---------------- bias1 permutation: fragment order per (h, warp, chunk) ----
// flat j = mt*16 + rowsel*8 + nt*2 + colpair; float4 i = j>>2
__global__ void prep_b1(const float* __restrict__ bias1) {
    int idx = blockIdx.x * 256 + threadIdx.x;   // 262144 total
    int x   = idx & 3;
    int lane = (idx >> 2) & 31;
    int i   = (idx >> 7) & 7;
    int c4  = (idx >> 10) & 7;
    int w   = (idx >> 13) & 7;
    int h   = idx >> 16;
    int j = i*4 + x;
    int colpair = j & 1;
    int nt      = (j >> 1) & 3;
    int rowsel  = (j >> 3) & 1;
    int mt      = (j >> 4) & 1;
    int g = lane >> 2, tg = lane & 3;
    int q = w*32 + mt*16 + rowsel*8 + g;
    int k = c4*32 + nt*8 + tg*2 + colpair;
    g_pb1[idx] = bias1[((size_t)h*SS + q)*SS + k];
}

// ---------------- projection GEMM (fp16 2-term: A single, W split) ----------
// MODE 0: X=q_x,  W=[Wq;Wg]: by0 -> Q split head layout (scaled), by1 -> sigmoid gate
// MODE 1: X=kv_x, W=[Wk;Wv]: by0 -> K single head layout, by1 -> V single
// MODE 2: A=g_O (fp16), W=Wo: out = y + bo (fp32)
#define AST 72
#define PROJ_SMEM (3*128*AST*2)   // A single + B hi + B lo = 55296 B

template<int MODE>
__global__ void __launch_bounds__(256, 2) proj_kernel(const float* __restrict__ X,
                                                      const float* __restrict__ bias,
                                                      float* __restrict__ outp)
{
    extern __shared__ __half sm[];
    __half* As = sm;
    __half* Bh = sm + 128*AST;
    __half* Bl = sm + 2*128*AST;

    const int tid = threadIdx.x;
    const int lane = tid & 31;
    const int w = tid >> 5;
    const int g = lane >> 2;
    const int tg = lane & 3;
    const int wm = w & 3;
    const int wn = w >> 2;
    const int m0 = blockIdx.x * 128;
    const int n0 = blockIdx.y * 128;

    // ldmatrix lane-address offsets
    const int arow = ((lane >> 3) & 1) * 8 + (lane & 7);  // m-order r0k0,r8k0,r0k8,r8k8
    const int acol = (lane >> 4) * 8;
    const int brow = (lane >> 4) * 8 + (lane & 7);        // m-order n0k0,n0k8,n8k0,n8k8
    const int bcol = ((lane >> 3) & 1) * 8;

    const __half *Wh, *Wl;
    if (MODE == 0)      { Wh = g_Wqg_h; Wl = g_Wqg_l; }
    else if (MODE == 1) { Wh = g_Wkv_h; Wl = g_Wkv_l; }
    else                { Wh = g_Wo_h;  Wl = g_Wo_l;  }

    float acc[2][8][4];
#pragma unroll
    for (int a = 0; a < 2; a++)
#pragma unroll
        for (int b = 0; b < 8; b++)
#pragma unroll
            for (int c = 0; c < 4; c++) acc[a][b][c] = 0.f;

    for (int ks = 0; ks < 2; ks++) {
        const int kbase = ks * 64;
        // --- stage A (single fp16) ---
        if (MODE < 2) {
#pragma unroll
            for (int i = 0; i < 8; i++) {
                int lin = tid + 256*i;            // float4 units
                int r = lin >> 4;
                int c = (lin & 15) * 4;
                float4 xv = *(const float4*)(X + (size_t)(m0+r)*CC + kbase + c);
                __half2 p01 = __floats2half2_rn(xv.x, xv.y);
                __half2 p23 = __floats2half2_rn(xv.z, xv.w);
                *(u32*)&As[r*AST+c]   = *(u32*)&p01;
                *(u32*)&As[r*AST+c+2] = *(u32*)&p23;
            }
        } else {
#pragma unroll
            for (int i = 0; i < 16; i++) {
                int lin = tid + 256*i;            // u32 units
                int r = lin >> 5;
                int c = (lin & 31) * 2;
                *(u32*)&As[r*AST+c] = *(const u32*)(g_O + (size_t)(m0+r)*CC + kbase + c);
            }
        }
        // --- stage B (weights split, [n][k] row-major) ---
#pragma unroll
        for (int i = 0; i < 16; i++) {
            int lin = tid + 256*i;
            int r = lin >> 5;
            int c = (lin & 31) * 2;
            *(u32*)&Bh[r*AST+c] = *(const u32*)(Wh + (size_t)(n0+r)*CC + kbase + c);
            *(u32*)&Bl[r*AST+c] = *(const u32*)(Wl + (size_t)(n0+r)*CC + kbase + c);
        }
        __syncthreads();

#pragma unroll
        for (int k16 = 0; k16 < 4; k16++) {
            const int k0 = k16 * 16;
            u32 a[2][4];
#pragma unroll
            for (int mt = 0; mt < 2; mt++)
                ldsm4(a[mt], &As[(wm*32 + mt*16 + arow)*AST + k0 + acol]);
#pragma unroll
            for (int np = 0; np < 4; np++) {
                u32 bhf[4], blf[4];
                ldsm4(bhf, &Bh[(wn*64 + np*16 + brow)*AST + k0 + bcol]);
                ldsm4(blf, &Bl[(wn*64 + np*16 + brow)*AST + k0 + bcol]);
#pragma unroll
                for (int half = 0; half < 2; half++) {
                    int nt = 2*np + half;
#pragma unroll
                    for (int mt = 0; mt < 2; mt++) {
                        mma_f16(acc[mt][nt], a[mt], &bhf[half*2]);
                        mma_f16(acc[mt][nt], a[mt], &blf[half*2]);
                    }
                }
            }
        }
        __syncthreads();
    }

    // --- epilogue ---
#pragma unroll
    for (int mt = 0; mt < 2; mt++) {
#pragma unroll
        for (int nt = 0; nt < 8; nt++) {
#pragma unroll
            for (int rr = 0; rr < 2; rr++) {
                int m   = m0 + wm*32 + mt*16 + g + rr*8;
                int col = wn*64 + nt*8 + tg*2;
                float y0 = acc[mt][nt][rr*2+0];
                float y1 = acc[mt][nt][rr*2+1];
                if (MODE == 2) {
                    float2 o; o.x = y0 + bias[col]; o.y = y1 + bias[col+1];
                    *(float2*)(outp + (size_t)m*CC + col) = o;
                } else if (blockIdx.y == 0) {
                    // Q (split) or K (single), head layout
                    int hh = col >> 5, d = col & 31;
                    int si = m >> 8,  j = m & 255;
                    size_t idx = (((size_t)si*HH + hh)*SS + j)*DD + d;
                    if (MODE == 0) {
                        y0 *= 0.17677669529663687f; y1 *= 0.17677669529663687f;
                        __half2 vh, vl;
                        split2h(y0, vh.x, vl.x);
                        split2h(y1, vh.y, vl.y);
                        *(__half2*)&g_Qh[idx] = vh;
                        *(__half2*)&g_Ql[idx] = vl;
                    } else {
                        *(__half2*)&g_K[idx] = __floats2half2_rn(y0, y1);
                    }
                } else {
                    if (MODE == 0) {
                        float s0 = 1.f/(1.f + __expf(-(y0 + bias[col])));
                        float s1 = 1.f/(1.f + __expf(-(y1 + bias[col+1])));
                        *(float2*)(g_G + (size_t)m*CC + col) = make_float2(s0, s1);
                    } else {
                        int hh = col >> 5, d = col & 31;
                        int si = m >> 8,  j = m & 255;
                        size_t idx = (((size_t)si*HH + hh)*SS + j)*DD + d;
                        *(__half2*)&g_V[idx] = __floats2half2_rn(y0, y1);
                    }
                }
            }
        }
    }
}

// ---------------- attention v6: fp16 2-term + fragment-ordered bias1 ----
// CTA = one (s,h): 256 threads / 8 warps; warp owns 32 q-rows x all 256 keys.
#define KST 40
#define VST 264
#define ATTN_SMEM (256*KST*2 + 32*VST*2 + 256*4)   // 38400 B

__global__ void __launch_bounds__(256, 2) attn_kernel(const float* __restrict__ bias2)
{
    extern __shared__ char smraw[];
    __half* Ksh = (__half*)smraw;                 // [256][KST]
    __half* Vth = Ksh + 256*KST;                  // [32][VST] (d-major, k across)
    float*  b2s = (float*)(Vth + 32*VST);         // [256]

    const int tid = threadIdx.x, lane = tid & 31, w = tid >> 5;
    const int g = lane >> 2, tg = lane & 3;
    const int h = blockIdx.x, s = blockIdx.y;
    const size_t headBase = ((size_t)s*HH + h) * SS * DD;

    // ---- stage K (coalesced uint4): 1024 uint4 ----
    {
        const uint4* sh = (const uint4*)(g_K + headBase);
#pragma unroll
        for (int it = 0; it < 4; it++) {
            int i = tid + it*256;
            int row = i >> 2, q4 = i & 3;
            *(uint4*)&Ksh[row*KST + q4*8] = sh[i];
        }
    }
    // ---- stage V transposed: Vt[d][k], one row per thread ----
    {
        const u32* sh = (const u32*)(g_V + headBase + (size_t)tid*DD);
#pragma unroll
        for (int j = 0; j < 16; j++) {
            int d = 2*j;
            u32 v = sh[j];
            __half2 p = *(__half2*)&v;
            Vth[ d   *VST + tid] = p.x;
            Vth[(d+1)*VST + tid] = p.y;
        }
    }
    b2s[tid] = bias2[(size_t)s*SS + tid];

    // ---- Q fragments (split), overlap staging ----
    const int q0 = w * 32;
    u32 qh[2][2][4], ql[2][2][4];
    {
        const u32* srcH = (const u32*)(g_Qh + headBase);
        const u32* srcL = (const u32*)(g_Ql + headBase);
#pragma unroll
        for (int mt = 0; mt < 2; mt++) {
            int r0 = q0 + mt*16 + g, r1 = r0 + 8;
#pragma unroll
            for (int sl2 = 0; sl2 < 2; sl2++) {
                int kc = sl2*8 + tg;
                qh[mt][sl2][0] = srcH[r0*16 + kc];
                qh[mt][sl2][1] = srcH[r1*16 + kc];
                qh[mt][sl2][2] = srcH[r0*16 + kc + 4];
                qh[mt][sl2][3] = srcH[r1*16 + kc + 4];
                ql[mt][sl2][0] = srcL[r0*16 + kc];
                ql[mt][sl2][1] = srcL[r1*16 + kc];
                ql[mt][sl2][2] = srcL[r0*16 + kc + 4];
                ql[mt][sl2][3] = srcL[r1*16 + kc + 4];
            }
        }
    }
    __syncthreads();

    float acc[2][4][4];
#pragma unroll
    for (int mt = 0; mt < 2; mt++)
#pragma unroll
        for (int a = 0; a < 4; a++)
#pragma unroll
            for (int b = 0; b < 4; b++) acc[mt][a][b] = 0.f;
    float m_a[2] = {-1e30f, -1e30f}, m_b[2] = {-1e30f, -1e30f};
    float l_a[2] = {0.f, 0.f},       l_b[2] = {0.f, 0.f};

    const int kr = lane & 7, kcb = lane >> 3;
    const int vr = lane & 7, vcb = (lane >> 3) & 1;

    // fragment-ordered bias1 base for this (h, warp, lane); per chunk: + c4*1024
    const float4* pb1base = (const float4*)(g_pb1 + ((((size_t)h*8 + w)*8)*8*32 + lane)*4);

#pragma unroll
    for (int c4 = 0; c4 < 8; c4++) {                   // 8 chunks of 32 keys
        const int n0c = c4 * 32;
        const float4* pb = pb1base + (size_t)c4 * 256;  // 8 i-blocks x 32 lanes
        // ---- QK^T ----
        float sc[2][4][4];
#pragma unroll
        for (int mt = 0; mt < 2; mt++)
#pragma unroll
            for (int nt = 0; nt < 4; nt++)
#pragma unroll
                for (int c = 0; c < 4; c++) sc[mt][nt][c] = 0.f;

#pragma unroll
        for (int nt = 0; nt < 4; nt++) {
            int n8 = n0c + nt*8;
            u32 kb[4];
            ldsm4(kb, &Ksh[(n8 + kr)*KST + kcb*8]);
#pragma unroll
            for (int mt = 0; mt < 2; mt++) {
#pragma unroll
                for (int sl2 = 0; sl2 < 2; sl2++) {
                    mma_f16(sc[mt][nt], qh[mt][sl2], &kb[sl2*2]);
                    mma_f16(sc[mt][nt], ql[mt][sl2], &kb[sl2*2]);
                }
            }
        }

        // ---- bias add (coalesced fragment-ordered) + per-row max, rescale ----
#pragma unroll
        for (int mt = 0; mt < 2; mt++) {
            float ta = -1e30f, tb = -1e30f;
#pragma unroll
            for (int np = 0; np < 2; np++) {
                float4 fa = pb[(mt*4 + np)*32];        // rowsel=0, nt = 2np, 2np+1
                float4 fb = pb[(mt*4 + 2 + np)*32];    // rowsel=1
#pragma unroll
                for (int half = 0; half < 2; half++) {
                    int nt = 2*np + half;
                    int c = n0c + nt*8 + tg*2;
                    float2 b2v = *(float2*)&b2s[c];
                    float bax = half ? fa.z : fa.x;
                    float bay = half ? fa.w : fa.y;
                    float bbx = half ? fb.z : fb.x;
                    float bby = half ? fb.w : fb.y;
                    sc[mt][nt][0] += bax + b2v.x;
                    sc[mt][nt][1] += bay + b2v.y;
                    sc[mt][nt][2] += bbx + b2v.x;
                    sc[mt][nt][3] += bby + b2v.y;
                    ta = fmaxf(ta, fmaxf(sc[mt][nt][0], sc[mt][nt][1]));
                    tb = fmaxf(tb, fmaxf(sc[mt][nt][2], sc[mt][nt][3]));
                }
            }
            ta = fmaxf(ta, __shfl_xor_sync(0xffffffffu, ta, 1));
            ta = fmaxf(ta, __shfl_xor_sync(0xffffffffu, ta, 2));
            tb = fmaxf(tb, __shfl_xor_sync(0xffffffffu, tb, 1));
            tb = fmaxf(tb, __shfl_xor_sync(0xffffffffu, tb, 2));

            float mna = fmaxf(m_a[mt], ta), mnb = fmaxf(m_b[mt], tb);
            float sca = __expf(m_a[mt] - mna), scb = __expf(m_b[mt] - mnb);
            m_a[mt] = mna; m_b[mt] = mnb;
            l_a[mt] *= sca; l_b[mt] *= scb;
#pragma unroll
            for (int nd = 0; nd < 4; nd++) {
                acc[mt][nd][0] *= sca; acc[mt][nd][1] *= sca;
                acc[mt][nd][2] *= scb; acc[mt][nd][3] *= scb;
            }
        }

        // ---- fused exp + split-fp16 pack + P·V per k16 ----
#pragma unroll
        for (int s8 = 0; s8 < 2; s8++) {
            u32 ah[2][4], al[2][4];
#pragma unroll
            for (int mt = 0; mt < 2; mt++) {
#pragma unroll
                for (int half = 0; half < 2; half++) {
                    int nt = 2*s8 + half;
                    float p0 = __expf(sc[mt][nt][0] - m_a[mt]);
                    float p1 = __expf(sc[mt][nt][1] - m_a[mt]);
                    float p2 = __expf(sc[mt][nt][2] - m_b[mt]);
                    float p3 = __expf(sc[mt][nt][3] - m_b[mt]);
                    l_a[mt] += p0 + p1;
                    l_b[mt] += p2 + p3;
                    __half2 hv, lv;
                    split2h(p0, hv.x, lv.x); split2h(p1, hv.y, lv.y);
                    ah[mt][half*2]     = *(u32*)&hv;  al[mt][half*2]     = *(u32*)&lv;
                    split2h(p2, hv.x, lv.x); split2h(p3, hv.y, lv.y);
                    ah[mt][half*2 + 1] = *(u32*)&hv;  al[mt][half*2 + 1] = *(u32*)&lv;
                }
            }
            int kkg = n0c + s8*16;
#pragma unroll
            for (int nd = 0; nd < 4; nd++) {
                u32 vb[2];
                ldsm2(vb, &Vth[(nd*8 + vr)*VST + kkg + vcb*8]);
#pragma unroll
                for (int mt = 0; mt < 2; mt++) {
                    mma_f16(acc[mt][nd], ah[mt], vb);
                    mma_f16(acc[mt][nd], al[mt], vb);
                }
            }
        }
    }

    // ---- reduce row-sums, epilogue: normalize, gate, fp16 store ----
#pragma unroll
    for (int mt = 0; mt < 2; mt++) {
        float la = l_a[mt], lb = l_b[mt];
        la += __shfl_xor_sync(0xffffffffu, la, 1);
        la += __shfl_xor_sync(0xffffffffu, la, 2);
        lb += __shfl_xor_sync(0xffffffffu, lb, 1);
        lb += __shfl_xor_sync(0xffffffffu, lb, 2);
        const float inva = 1.0f / la;
        const float invb = 1.0f / lb;
        const int ta_t = s*SS + q0 + mt*16 + g;
        const int tb_t = ta_t + 8;
#pragma unroll
        for (int nd = 0; nd < 4; nd++) {
            int col = h*DD + nd*8 + tg*2;
            float2 ga = *(const float2*)(g_G + (size_t)ta_t*CC + col);
            float2 gb = *(const float2*)(g_G + (size_t)tb_t*CC + col);
            float o0 = acc[mt][nd][0] * inva * ga.x;
            float o1 = acc[mt][nd][1] * inva * ga.y;
            float o2 = acc[mt][nd][2] * invb * gb.x;
            float o3 = acc[mt][nd][3] * invb * gb.y;
            *(__half2*)&g_O[(size_t)ta_t*CC + col] = __floats2half2_rn(o0, o1);
            *(__half2*)&g_O[(size_t)tb_t*CC + col] = __floats2half2_rn(o2, o3);
        }
    }
}

// ---------------- launch ----------------
extern "C" void kernel_launch(void* const* d_in, const int* in_sizes, int n_in,
                              void* d_out, int out_size)
{
    const float* q_x   = (const float*)d_in[0];
    const float* kv_x  = (const float*)d_in[1];
    const float* bias1 = (const float*)d_in[2];
    const float* bias2 = (const float*)d_in[3];
    const float* bg    = (const float*)d_in[8];
    const float* bo    = (const float*)d_in[10];
    float* out = (float*)d_out;

    cudaFuncSetAttribute(proj_kernel<0>, cudaFuncAttributeMaxDynamicSharedMemorySize, PROJ_SMEM);
    cudaFuncSetAttribute(proj_kernel<1>, cudaFuncAttributeMaxDynamicSharedMemorySize, PROJ_SMEM);
    cudaFuncSetAttribute(proj_kernel<2>, cudaFuncAttributeMaxDynamicSharedMemorySize, PROJ_SMEM);
    cudaFuncSetAttribute(attn_kernel,    cudaFuncAttributeMaxDynamicSharedMemorySize, ATTN_SMEM);

    prep_w<<<64, 256>>>((const float*)d_in[4], (const float*)d_in[5],
                        (const float*)d_in[6], (const float*)d_in[7],
                        (const float*)d_in[9]);
    prep_b1<<<1024, 256>>>(bias1);
    proj_kernel<0><<<dim3(512, 2), 256, PROJ_SMEM>>>(q_x,  bg, nullptr);
    proj_kernel<1><<<dim3(512, 2), 256, PROJ_SMEM>>>(kv_x, nullptr, nullptr);
    attn_kernel<<<dim3(HH, SS), 256, ATTN_SMEM>>>(bias2);
    proj_kernel<2><<<dim3(512, 1), 256, PROJ_SMEM>>>(nullptr, bo, out);
}

// round 13
// speedup vs baseline: 1.6037x; 1.0808x over previous
#include <cuda_runtime.h>
#include <cuda_fp16.h>

#define SS 256
#define CC 128
#define HH 4
#define DD 32
#define TT (SS*SS)

typedef unsigned int u32;

// ---------------- global scratch (no allocations allowed) ----------------
#define NQ (SS*HH*SS*DD)   // 8,388,608
__device__ __half g_Qh[NQ], g_Ql[NQ];          // Q split (A operand of QK^T)
__device__ __half g_K [NQ];                    // K single fp16
__device__ __half g_V [NQ];                    // V single fp16
__device__ float  g_G [(size_t)TT*CC];
__device__ __half g_O [(size_t)TT*CC];         // attn output single fp16
__device__ __half g_Wqg_h[2*CC*CC], g_Wqg_l[2*CC*CC];   // weights split
__device__ __half g_Wkv_h[2*CC*CC], g_Wkv_l[2*CC*CC];
__device__ __half g_Wo_h [CC*CC],   g_Wo_l [CC*CC];
// fragment-ordered bias1 permutation: [h][w][c4][i][lane][4]
__device__ float  g_pb1[4*8*8*8*32*4];         // 1 MB

__device__ __forceinline__ void split2h(float v, __half& h, __half& l) {
    h = __float2half_rn(v);
    l = __float2half_rn(v - __half2float(h));
}

__device__ __forceinline__ void mma_f16(float* d, const u32* a, const u32* b) {
    asm volatile(
      "mma.sync.aligned.m16n8k16.row.col.f32.f16.f16.f32 "
      "{%0,%1,%2,%3}, {%4,%5,%6,%7}, {%8,%9}, {%0,%1,%2,%3};\n"
      : "+f"(d[0]), "+f"(d[1]), "+f"(d[2]), "+f"(d[3])
      : "r"(a[0]), "r"(a[1]), "r"(a[2]), "r"(a[3]), "r"(b[0]), "r"(b[1]));
}

__device__ __forceinline__ void ldsm4(u32* r, const void* p) {
    u32 a = (u32)__cvta_generic_to_shared(p);
    asm volatile("ldmatrix.sync.aligned.m8n8.x4.shared.b16 {%0,%1,%2,%3}, [%4];"
                 : "=r"(r[0]), "=r"(r[1]), "=r"(r[2]), "=r"(r[3]) : "r"(a));
}
__device__ __forceinline__ void ldsm2t(u32* r, const void* p) {
    u32 a = (u32)__cvta_generic_to_shared(p);
    asm volatile("ldmatrix.sync.aligned.m8n8.x2.trans.shared.b16 {%0,%1}, [%2];"
                 : "=r"(r[0]), "=r"(r[1]) : "r"(a));
}

// ---------------- merged prep: weights split + bias1 permutation ----------
__global__ void prep_all(const float* __restrict__ wq, const float* __restrict__ wk,
                         const float* __restrict__ wv, const float* __restrict__ wg,
                         const float* __restrict__ wo, const float* __restrict__ bias1) {
    int idx = blockIdx.x * 256 + threadIdx.x;   // 262144 total
    if (idx < CC*CC) {
        int i = idx;
        split2h(wq[i], g_Wqg_h[i],         g_Wqg_l[i]);
        split2h(wg[i], g_Wqg_h[CC*CC + i], g_Wqg_l[CC*CC + i]);
        split2h(wk[i], g_Wkv_h[i],         g_Wkv_l[i]);
        split2h(wv[i], g_Wkv_h[CC*CC + i], g_Wkv_l[CC*CC + i]);
        split2h(wo[i], g_Wo_h[i],          g_Wo_l[i]);
    }
    // bias1 permutation: flat j = mt*16 + rowsel*8 + nt*2 + colpair
    int x    = idx & 3;
    int lane = (idx >> 2) & 31;
    int i4   = (idx >> 7) & 7;
    int c4   = (idx >> 10) & 7;
    int w    = (idx >> 13) & 7;
    int h    = idx >> 16;
    int j = i4*4 + x;
    int colpair = j & 1;
    int nt      = (j >> 1) & 3;
    int rowsel  = (j >> 3) & 1;
    int mt      = (j >> 4) & 1;
    int g = lane >> 2, tg = lane & 3;
    int q = w*32 + mt*16 + rowsel*8 + g;
    int k = c4*32 + nt*8 + tg*2 + colpair;
    g_pb1[idx] = bias1[((size_t)h*SS + q)*SS + k];
}

// ---------------- fused input projection (fp16 2-term: A single, W split) --
// grid (512, 4): mode = blockIdx.y>>1 (0: q_x->[Wq;Wg], 1: kv_x->[Wk;Wv]),
//                ny = blockIdx.y&1 (N-half).
#define AST 72
#define PROJ_SMEM (3*128*AST*2)   // 55296 B

__global__ void __launch_bounds__(256, 2) proj01(const float* __restrict__ q_x,
                                                 const float* __restrict__ kv_x,
                                                 const float* __restrict__ bg)
{
    extern __shared__ __half sm[];
    __half* As = sm;
    __half* Bh = sm + 128*AST;
    __half* Bl = sm + 2*128*AST;

    const int tid = threadIdx.x;
    const int lane = tid & 31;
    const int w = tid >> 5;
    const int g = lane >> 2;
    const int tg = lane & 3;
    const int wm = w & 3;
    const int wn = w >> 2;
    const int m0 = blockIdx.x * 128;
    const int mode = blockIdx.y >> 1;
    const int ny = blockIdx.y & 1;
    const int n0 = ny * 128;

    const int arow = ((lane >> 3) & 1) * 8 + (lane & 7);
    const int acol = (lane >> 4) * 8;
    const int brow = (lane >> 4) * 8 + (lane & 7);
    const int bcol = ((lane >> 3) & 1) * 8;

    const float* X = mode ? kv_x : q_x;
    const __half* Wh = mode ? g_Wkv_h : g_Wqg_h;
    const __half* Wl = mode ? g_Wkv_l : g_Wqg_l;

    float acc[2][8][4];
#pragma unroll
    for (int a = 0; a < 2; a++)
#pragma unroll
        for (int b = 0; b < 8; b++)
#pragma unroll
            for (int c = 0; c < 4; c++) acc[a][b][c] = 0.f;

    for (int ks = 0; ks < 2; ks++) {
        const int kbase = ks * 64;
#pragma unroll
        for (int i = 0; i < 8; i++) {
            int lin = tid + 256*i;
            int r = lin >> 4;
            int c = (lin & 15) * 4;
            float4 xv = *(const float4*)(X + (size_t)(m0+r)*CC + kbase + c);
            __half2 p01 = __floats2half2_rn(xv.x, xv.y);
            __half2 p23 = __floats2half2_rn(xv.z, xv.w);
            *(u32*)&As[r*AST+c]   = *(u32*)&p01;
            *(u32*)&As[r*AST+c+2] = *(u32*)&p23;
        }
#pragma unroll
        for (int i = 0; i < 16; i++) {
            int lin = tid + 256*i;
            int r = lin >> 5;
            int c = (lin & 31) * 2;
            *(u32*)&Bh[r*AST+c] = *(const u32*)(Wh + (size_t)(n0+r)*CC + kbase + c);
            *(u32*)&Bl[r*AST+c] = *(const u32*)(Wl + (size_t)(n0+r)*CC + kbase + c);
        }
        __syncthreads();

#pragma unroll
        for (int k16 = 0; k16 < 4; k16++) {
            const int k0 = k16 * 16;
            u32 a[2][4];
#pragma unroll
            for (int mt = 0; mt < 2; mt++)
                ldsm4(a[mt], &As[(wm*32 + mt*16 + arow)*AST + k0 + acol]);
#pragma unroll
            for (int np = 0; np < 4; np++) {
                u32 bhf[4], blf[4];
                ldsm4(bhf, &Bh[(wn*64 + np*16 + brow)*AST + k0 + bcol]);
                ldsm4(blf, &Bl[(wn*64 + np*16 + brow)*AST + k0 + bcol]);
#pragma unroll
                for (int half = 0; half < 2; half++) {
                    int nt = 2*np + half;
#pragma unroll
                    for (int mt = 0; mt < 2; mt++) {
                        mma_f16(acc[mt][nt], a[mt], &bhf[half*2]);
                        mma_f16(acc[mt][nt], a[mt], &blf[half*2]);
                    }
                }
            }
        }
        __syncthreads();
    }

    // --- epilogue ---
#pragma unroll
    for (int mt = 0; mt < 2; mt++) {
#pragma unroll
        for (int nt = 0; nt < 8; nt++) {
#pragma unroll
            for (int rr = 0; rr < 2; rr++) {
                int m   = m0 + wm*32 + mt*16 + g + rr*8;
                int col = wn*64 + nt*8 + tg*2;
                float y0 = acc[mt][nt][rr*2+0];
                float y1 = acc[mt][nt][rr*2+1];
                int hh = col >> 5, d = col & 31;
                int si = m >> 8,  j = m & 255;
                size_t idx = (((size_t)si*HH + hh)*SS + j)*DD + d;
                if (mode == 0) {
                    if (ny == 0) {
                        y0 *= 0.17677669529663687f; y1 *= 0.17677669529663687f;
                        __half2 vh, vl;
                        split2h(y0, vh.x, vl.x);
                        split2h(y1, vh.y, vl.y);
                        *(__half2*)&g_Qh[idx] = vh;
                        *(__half2*)&g_Ql[idx] = vl;
                    } else {
                        float s0 = 1.f/(1.f + __expf(-(y0 + bg[col])));
                        float s1 = 1.f/(1.f + __expf(-(y1 + bg[col+1])));
                        *(float2*)(g_G + (size_t)m*CC + col) = make_float2(s0, s1);
                    }
                } else {
                    __half2 v = __floats2half2_rn(y0, y1);
                    if (ny == 0) *(__half2*)&g_K[idx] = v;
                    else         *(__half2*)&g_V[idx] = v;
                }
            }
        }
    }
}

// ---------------- output projection (fp16 2-term, A = g_O) ----------------
__global__ void __launch_bounds__(256, 2) proj2(const float* __restrict__ bo,
                                                float* __restrict__ outp)
{
    extern __shared__ __half sm[];
    __half* As = sm;
    __half* Bh = sm + 128*AST;
    __half* Bl = sm + 2*128*AST;

    const int tid = threadIdx.x;
    const int lane = tid & 31;
    const int w = tid >> 5;
    const int g = lane >> 2;
    const int tg = lane & 3;
    const int wm = w & 3;
    const int wn = w >> 2;
    const int m0 = blockIdx.x * 128;

    const int arow = ((lane >> 3) & 1) * 8 + (lane & 7);
    const int acol = (lane >> 4) * 8;
    const int brow = (lane >> 4) * 8 + (lane & 7);
    const int bcol = ((lane >> 3) & 1) * 8;

    float acc[2][8][4];
#pragma unroll
    for (int a = 0; a < 2; a++)
#pragma unroll
        for (int b = 0; b < 8; b++)
#pragma unroll
            for (int c = 0; c < 4; c++) acc[a][b][c] = 0.f;

    for (int ks = 0; ks < 2; ks++) {
        const int kbase = ks * 64;
#pragma unroll
        for (int i = 0; i < 16; i++) {
            int lin = tid + 256*i;
            int r = lin >> 5;
            int c = (lin & 31) * 2;
            *(u32*)&As[r*AST+c] = *(const u32*)(g_O + (size_t)(m0+r)*CC + kbase + c);
        }
#pragma unroll
        for (int i = 0; i < 16; i++) {
            int lin = tid + 256*i;
            int r = lin >> 5;
            int c = (lin & 31) * 2;
            *(u32*)&Bh[r*AST+c] = *(const u32*)(g_Wo_h + (size_t)r*CC + kbase + c);
            *(u32*)&Bl[r*AST+c] = *(const u32*)(g_Wo_l + (size_t)r*CC + kbase + c);
        }
        __syncthreads();

#pragma unroll
        for (int k16 = 0; k16 < 4; k16++) {
            const int k0 = k16 * 16;
            u32 a[2][4];
#pragma unroll
            for (int mt = 0; mt < 2; mt++)
                ldsm4(a[mt], &As[(wm*32 + mt*16 + arow)*AST + k0 + acol]);
#pragma unroll
            for (int np = 0; np < 4; np++) {
                u32 bhf[4], blf[4];
                ldsm4(bhf, &Bh[(wn*64 + np*16 + brow)*AST + k0 + bcol]);
                ldsm4(blf, &Bl[(wn*64 + np*16 + brow)*AST + k0 + bcol]);
#pragma unroll
                for (int half = 0; half < 2; half++) {
                    int nt = 2*np + half;
#pragma unroll
                    for (int mt = 0; mt < 2; mt++) {
                        mma_f16(acc[mt][nt], a[mt], &bhf[half*2]);
                        mma_f16(acc[mt][nt], a[mt], &blf[half*2]);
                    }
                }
            }
        }
        __syncthreads();
    }

#pragma unroll
    for (int mt = 0; mt < 2; mt++) {
#pragma unroll
        for (int nt = 0; nt < 8; nt++) {
#pragma unroll
            for (int rr = 0; rr < 2; rr++) {
                int m   = m0 + wm*32 + mt*16 + g + rr*8;
                int col = wn*64 + nt*8 + tg*2;
                float2 o;
                o.x = acc[mt][nt][rr*2+0] + bo[col];
                o.y = acc[mt][nt][rr*2+1] + bo[col+1];
                *(float2*)(outp + (size_t)m*CC + col) = o;
            }
        }
    }
}

// ---------------- attention v7: fp16 2-term, V via ldmatrix.trans ----------
#define KST 40
#define ATTN_SMEM (2*256*KST*2 + 256*4)   // 41984 B

__global__ void __launch_bounds__(256, 2) attn_kernel(const float* __restrict__ bias2)
{
    extern __shared__ char smraw[];
    __half* Ksh = (__half*)smraw;                 // [256][KST]
    __half* Vsh = Ksh + 256*KST;                  // [256][KST]  (k rows, d cols)
    float*  b2s = (float*)(Vsh + 256*KST);        // [256]

    const int tid = threadIdx.x, lane = tid & 31, w = tid >> 5;
    const int g = lane >> 2, tg = lane & 3;
    const int h = blockIdx.x, s = blockIdx.y;
    const size_t headBase = ((size_t)s*HH + h) * SS * DD;

    // ---- stage K and V (both coalesced uint4, same layout) ----
    {
        const uint4* kh4 = (const uint4*)(g_K + headBase);
        const uint4* vh4 = (const uint4*)(g_V + headBase);
#pragma unroll
        for (int it = 0; it < 4; it++) {
            int i = tid + it*256;
            int row = i >> 2, q4 = i & 3;
            *(uint4*)&Ksh[row*KST + q4*8] = kh4[i];
            *(uint4*)&Vsh[row*KST + q4*8] = vh4[i];
        }
    }
    b2s[tid] = bias2[(size_t)s*SS + tid];

    // ---- Q fragments (split), overlap staging ----
    const int q0 = w * 32;
    u32 qh[2][2][4], ql[2][2][4];
    {
        const u32* srcH = (const u32*)(g_Qh + headBase);
        const u32* srcL = (const u32*)(g_Ql + headBase);
#pragma unroll
        for (int mt = 0; mt < 2; mt++) {
            int r0 = q0 + mt*16 + g, r1 = r0 + 8;
#pragma unroll
            for (int sl2 = 0; sl2 < 2; sl2++) {
                int kc = sl2*8 + tg;
                qh[mt][sl2][0] = srcH[r0*16 + kc];
                qh[mt][sl2][1] = srcH[r1*16 + kc];
                qh[mt][sl2][2] = srcH[r0*16 + kc + 4];
                qh[mt][sl2][3] = srcH[r1*16 + kc + 4];
                ql[mt][sl2][0] = srcL[r0*16 + kc];
                ql[mt][sl2][1] = srcL[r1*16 + kc];
                ql[mt][sl2][2] = srcL[r0*16 + kc + 4];
                ql[mt][sl2][3] = srcL[r1*16 + kc + 4];
            }
        }
    }
    __syncthreads();

    float acc[2][4][4];
#pragma unroll
    for (int mt = 0; mt < 2; mt++)
#pragma unroll
        for (int a = 0; a < 4; a++)
#pragma unroll
            for (int b = 0; b < 4; b++) acc[mt][a][b] = 0.f;
    float m_a[2] = {-1e30f, -1e30f}, m_b[2] = {-1e30f, -1e30f};
    float l_a[2] = {0.f, 0.f},       l_b[2] = {0.f, 0.f};

    const int kr = lane & 7, kcb = lane >> 3;
    const int vrow = ((lane >> 3) & 1) * 8 + (lane & 7);   // trans ldsm2 row

    const float4* pb1base = (const float4*)(g_pb1 + ((((size_t)h*8 + w)*8)*8*32 + lane)*4);

#pragma unroll
    for (int c4 = 0; c4 < 8; c4++) {                   // 8 chunks of 32 keys
        const int n0c = c4 * 32;
        const float4* pb = pb1base + (size_t)c4 * 256;
        // ---- QK^T ----
        float sc[2][4][4];
#pragma unroll
        for (int mt = 0; mt < 2; mt++)
#pragma unroll
            for (int nt = 0; nt < 4; nt++)
#pragma unroll
                for (int c = 0; c < 4; c++) sc[mt][nt][c] = 0.f;

#pragma unroll
        for (int nt = 0; nt < 4; nt++) {
            int n8 = n0c + nt*8;
            u32 kb[4];
            ldsm4(kb, &Ksh[(n8 + kr)*KST + kcb*8]);
#pragma unroll
            for (int mt = 0; mt < 2; mt++) {
#pragma unroll
                for (int sl2 = 0; sl2 < 2; sl2++) {
                    mma_f16(sc[mt][nt], qh[mt][sl2], &kb[sl2*2]);
                    mma_f16(sc[mt][nt], ql[mt][sl2], &kb[sl2*2]);
                }
            }
        }

        // ---- bias add (fragment-ordered) + per-row max, rescale ----
#pragma unroll
        for (int mt = 0; mt < 2; mt++) {
            float ta = -1e30f, tb = -1e30f;
#pragma unroll
            for (int np = 0; np < 2; np++) {
                float4 fa = pb[(mt*4 + np)*32];
                float4 fb = pb[(mt*4 + 2 + np)*32];
#pragma unroll
                for (int half = 0; half < 2; half++) {
                    int nt = 2*np + half;
                    int c = n0c + nt*8 + tg*2;
                    float2 b2v = *(float2*)&b2s[c];
                    float bax = half ? fa.z : fa.x;
                    float bay = half ? fa.w : fa.y;
                    float bbx = half ? fb.z : fb.x;
                    float bby = half ? fb.w : fb.y;
                    sc[mt][nt][0] += bax + b2v.x;
                    sc[mt][nt][1] += bay + b2v.y;
                    sc[mt][nt][2] += bbx + b2v.x;
                    sc[mt][nt][3] += bby + b2v.y;
                    ta = fmaxf(ta, fmaxf(sc[mt][nt][0], sc[mt][nt][1]));
                    tb = fmaxf(tb, fmaxf(sc[mt][nt][2], sc[mt][nt][3]));
                }
            }
            ta = fmaxf(ta, __shfl_xor_sync(0xffffffffu, ta, 1));
            ta = fmaxf(ta, __shfl_xor_sync(0xffffffffu, ta, 2));
            tb = fmaxf(tb, __shfl_xor_sync(0xffffffffu, tb, 1));
            tb = fmaxf(tb, __shfl_xor_sync(0xffffffffu, tb, 2));

            float mna = fmaxf(m_a[mt], ta), mnb = fmaxf(m_b[mt], tb);
            float sca = __expf(m_a[mt] - mna), scb = __expf(m_b[mt] - mnb);
            m_a[mt] = mna; m_b[mt] = mnb;
            l_a[mt] *= sca; l_b[mt] *= scb;
#pragma unroll
            for (int nd = 0; nd < 4; nd++) {
                acc[mt][nd][0] *= sca; acc[mt][nd][1] *= sca;
                acc[mt][nd][2] *= scb; acc[mt][nd][3] *= scb;
            }
        }

        // ---- fused exp + split-fp16 pack + P·V per k16 (V via trans ldsm) ----
#pragma unroll
        for (int s8 = 0; s8 < 2; s8++) {
            u32 ah[2][4], al[2][4];
#pragma unroll
            for (int mt = 0; mt < 2; mt++) {
#pragma unroll
                for (int half = 0; half < 2; half++) {
                    int nt = 2*s8 + half;
                    float p0 = __expf(sc[mt][nt][0] - m_a[mt]);
                    float p1 = __expf(sc[mt][nt][1] - m_a[mt]);
                    float p2 = __expf(sc[mt][nt][2] - m_b[mt]);
                    float p3 = __expf(sc[mt][nt][3] - m_b[mt]);
                    l_a[mt] += p0 + p1;
                    l_b[mt] += p2 + p3;
                    __half2 hv, lv;
                    split2h(p0, hv.x, lv.x); split2h(p1, hv.y, lv.y);
                    ah[mt][half*2]     = *(u32*)&hv;  al[mt][half*2]     = *(u32*)&lv;
                    split2h(p2, hv.x, lv.x); split2h(p3, hv.y, lv.y);
                    ah[mt][half*2 + 1] = *(u32*)&hv;  al[mt][half*2 + 1] = *(u32*)&lv;
                }
            }
            int kkg = n0c + s8*16;
#pragma unroll
            for (int nd = 0; nd < 4; nd++) {
                u32 vb[2];
                ldsm2t(vb, &Vsh[(kkg + vrow)*KST + nd*8]);
#pragma unroll
                for (int mt = 0; mt < 2; mt++) {
                    mma_f16(acc[mt][nd], ah[mt], vb);
                    mma_f16(acc[mt][nd], al[mt], vb);
                }
            }
        }
    }

    // ---- reduce row-sums, epilogue: normalize, gate, fp16 store ----
#pragma unroll
    for (int mt = 0; mt < 2; mt++) {
        float la = l_a[mt], lb = l_b[mt];
        la += __shfl_xor_sync(0xffffffffu, la, 1);
        la += __shfl_xor_sync(0xffffffffu, la, 2);
        lb += __shfl_xor_sync(0xffffffffu, lb, 1);
        lb += __shfl_xor_sync(0xffffffffu, lb, 2);
        const float inva = 1.0f / la;
        const float invb = 1.0f / lb;
        const int ta_t = s*SS + q0 + mt*16 + g;
        const int tb_t = ta_t + 8;
#pragma unroll
        for (int nd = 0; nd < 4; nd++) {
            int col = h*DD + nd*8 + tg*2;
            float2 ga = *(const float2*)(g_G + (size_t)ta_t*CC + col);
            float2 gb = *(const float2*)(g_G + (size_t)tb_t*CC + col);
            float o0 = acc[mt][nd][0] * inva * ga.x;
            float o1 = acc[mt][nd][1] * inva * ga.y;
            float o2 = acc[mt][nd][2] * invb * gb.x;
            float o3 = acc[mt][nd][3] * invb * gb.y;
            *(__half2*)&g_O[(size_t)ta_t*CC + col] = __floats2half2_rn(o0, o1);
            *(__half2*)&g_O[(size_t)tb_t*CC + col] = __floats2half2_rn(o2, o3);
        }
    }
}

// ---------------- launch ----------------
extern "C" void kernel_launch(void* const* d_in, const int* in_sizes, int n_in,
                              void* d_out, int out_size)
{
    const float* q_x   = (const float*)d_in[0];
    const float* kv_x  = (const float*)d_in[1];
    const float* bias1 = (const float*)d_in[2];
    const float* bias2 = (const float*)d_in[3];
    const float* bg    = (const float*)d_in[8];
    const float* bo    = (const float*)d_in[10];
    float* out = (float*)d_out;

    cudaFuncSetAttribute(proj01,      cudaFuncAttributeMaxDynamicSharedMemorySize, PROJ_SMEM);
    cudaFuncSetAttribute(proj2,       cudaFuncAttributeMaxDynamicSharedMemorySize, PROJ_SMEM);
    cudaFuncSetAttribute(attn_kernel, cudaFuncAttributeMaxDynamicSharedMemorySize, ATTN_SMEM);

    prep_all<<<1024, 256>>>((const float*)d_in[4], (const float*)d_in[5],
                            (const float*)d_in[6], (const float*)d_in[7],
                            (const float*)d_in[9], bias1);
    proj01<<<dim3(512, 4), 256, PROJ_SMEM>>>(q_x, kv_x, bg);
    attn_kernel<<<dim3(HH, SS), 256, ATTN_SMEM>>>(bias2);
    proj2<<<512, 256, PROJ_SMEM>>>(bo, out);
}

// round 14
// speedup vs baseline: 1.7342x; 1.0813x over previous
#include <cuda_runtime.h>
#include <cuda_fp16.h>

#define SS 256
#define CC 128
#define HH 4
#define DD 32
#define TT (SS*SS)

typedef unsigned int u32;

// ---------------- global scratch (no allocations allowed) ----------------
#define NQ (SS*HH*SS*DD)   // 8,388,608
__device__ __half g_Qh[NQ], g_Ql[NQ];          // Q split (A operand of QK^T)
__device__ __half g_K [NQ];                    // K single fp16
__device__ __half g_V [NQ];                    // V single fp16
__device__ float  g_G [(size_t)TT*CC];
__device__ __half g_O [(size_t)TT*CC];         // attn output single fp16
__device__ __half g_Wqg_h[2*CC*CC], g_Wqg_l[2*CC*CC];   // weights split
__device__ __half g_Wkv_h[2*CC*CC], g_Wkv_l[2*CC*CC];
__device__ __half g_Wo_h [CC*CC],   g_Wo_l [CC*CC];
// fragment-ordered bias1 permutation: [h][w][c4][i][lane][4]
__device__ float  g_pb1[4*8*8*8*32*4];         // 1 MB

__device__ __forceinline__ void split2h(float v, __half& h, __half& l) {
    h = __float2half_rn(v);
    l = __float2half_rn(v - __half2float(h));
}

__device__ __forceinline__ void mma_f16(float* d, const u32* a, const u32* b) {
    asm volatile(
      "mma.sync.aligned.m16n8k16.row.col.f32.f16.f16.f32 "
      "{%0,%1,%2,%3}, {%4,%5,%6,%7}, {%8,%9}, {%0,%1,%2,%3};\n"
      : "+f"(d[0]), "+f"(d[1]), "+f"(d[2]), "+f"(d[3])
      : "r"(a[0]), "r"(a[1]), "r"(a[2]), "r"(a[3]), "r"(b[0]), "r"(b[1]));
}

__device__ __forceinline__ void ldsm4(u32* r, const void* p) {
    u32 a = (u32)__cvta_generic_to_shared(p);
    asm volatile("ldmatrix.sync.aligned.m8n8.x4.shared.b16 {%0,%1,%2,%3}, [%4];"
                 : "=r"(r[0]), "=r"(r[1]), "=r"(r[2]), "=r"(r[3]) : "r"(a));
}
__device__ __forceinline__ void ldsm2t(u32* r, const void* p) {
    u32 a = (u32)__cvta_generic_to_shared(p);
    asm volatile("ldmatrix.sync.aligned.m8n8.x2.trans.shared.b16 {%0,%1}, [%2];"
                 : "=r"(r[0]), "=r"(r[1]) : "r"(a));
}

// ---------------- merged prep: weights split + bias1 permutation ----------
__global__ void prep_all(const float* __restrict__ wq, const float* __restrict__ wk,
                         const float* __restrict__ wv, const float* __restrict__ wg,
                         const float* __restrict__ wo, const float* __restrict__ bias1) {
    int idx = blockIdx.x * 256 + threadIdx.x;   // 262144 total
    if (idx < CC*CC) {
        int i = idx;
        split2h(wq[i], g_Wqg_h[i],         g_Wqg_l[i]);
        split2h(wg[i], g_Wqg_h[CC*CC + i], g_Wqg_l[CC*CC + i]);
        split2h(wk[i], g_Wkv_h[i],         g_Wkv_l[i]);
        split2h(wv[i], g_Wkv_h[CC*CC + i], g_Wkv_l[CC*CC + i]);
        split2h(wo[i], g_Wo_h[i],          g_Wo_l[i]);
    }
    // bias1 permutation: flat j = mt*16 + rowsel*8 + nt*2 + colpair
    int x    = idx & 3;
    int lane = (idx >> 2) & 31;
    int i4   = (idx >> 7) & 7;
    int c4   = (idx >> 10) & 7;
    int w    = (idx >> 13) & 7;
    int h    = idx >> 16;
    int j = i4*4 + x;
    int colpair = j & 1;
    int nt      = (j >> 1) & 3;
    int rowsel  = (j >> 3) & 1;
    int mt      = (j >> 4) & 1;
    int g = lane >> 2, tg = lane & 3;
    int q = w*32 + mt*16 + rowsel*8 + g;
    int k = c4*32 + nt*8 + tg*2 + colpair;
    g_pb1[idx] = bias1[((size_t)h*SS + q)*SS + k];
}

// ---------------- fused input projection (fp16 2-term: A single, W split) --
// grid (512, 4): mode = blockIdx.y>>1 (0: q_x->[Wq;Wg], 1: kv_x->[Wk;Wv]),
//                ny = blockIdx.y&1 (N-half).
#define AST 72
#define PROJ_SMEM (3*128*AST*2)   // 55296 B

__global__ void __launch_bounds__(256, 2) proj01(const float* __restrict__ q_x,
                                                 const float* __restrict__ kv_x,
                                                 const float* __restrict__ bg)
{
    extern __shared__ __half sm[];
    __half* As = sm;
    __half* Bh = sm + 128*AST;
    __half* Bl = sm + 2*128*AST;

    const int tid = threadIdx.x;
    const int lane = tid & 31;
    const int w = tid >> 5;
    const int g = lane >> 2;
    const int tg = lane & 3;
    const int wm = w & 3;
    const int wn = w >> 2;
    const int m0 = blockIdx.x * 128;
    const int mode = blockIdx.y >> 1;
    const int ny = blockIdx.y & 1;
    const int n0 = ny * 128;

    const int arow = ((lane >> 3) & 1) * 8 + (lane & 7);
    const int acol = (lane >> 4) * 8;
    const int brow = (lane >> 4) * 8 + (lane & 7);
    const int bcol = ((lane >> 3) & 1) * 8;

    const float* X = mode ? kv_x : q_x;
    const __half* Wh = mode ? g_Wkv_h : g_Wqg_h;
    const __half* Wl = mode ? g_Wkv_l : g_Wqg_l;

    float acc[2][8][4];
#pragma unroll
    for (int a = 0; a < 2; a++)
#pragma unroll
        for (int b = 0; b < 8; b++)
#pragma unroll
            for (int c = 0; c < 4; c++) acc[a][b][c] = 0.f;

    for (int ks = 0; ks < 2; ks++) {
        const int kbase = ks * 64;
#pragma unroll
        for (int i = 0; i < 8; i++) {
            int lin = tid + 256*i;
            int r = lin >> 4;
            int c = (lin & 15) * 4;
            float4 xv = *(const float4*)(X + (size_t)(m0+r)*CC + kbase + c);
            __half2 p01 = __floats2half2_rn(xv.x, xv.y);
            __half2 p23 = __floats2half2_rn(xv.z, xv.w);
            *(u32*)&As[r*AST+c]   = *(u32*)&p01;
            *(u32*)&As[r*AST+c+2] = *(u32*)&p23;
        }
#pragma unroll
        for (int i = 0; i < 16; i++) {
            int lin = tid + 256*i;
            int r = lin >> 5;
            int c = (lin & 31) * 2;
            *(u32*)&Bh[r*AST+c] = *(const u32*)(Wh + (size_t)(n0+r)*CC + kbase + c);
            *(u32*)&Bl[r*AST+c] = *(const u32*)(Wl + (size_t)(n0+r)*CC + kbase + c);
        }
        __syncthreads();

#pragma unroll
        for (int k16 = 0; k16 < 4; k16++) {
            const int k0 = k16 * 16;
            u32 a[2][4];
#pragma unroll
            for (int mt = 0; mt < 2; mt++)
                ldsm4(a[mt], &As[(wm*32 + mt*16 + arow)*AST + k0 + acol]);
#pragma unroll
            for (int np = 0; np < 4; np++) {
                u32 bhf[4], blf[4];
                ldsm4(bhf, &Bh[(wn*64 + np*16 + brow)*AST + k0 + bcol]);
                ldsm4(blf, &Bl[(wn*64 + np*16 + brow)*AST + k0 + bcol]);
#pragma unroll
                for (int half = 0; half < 2; half++) {
                    int nt = 2*np + half;
#pragma unroll
                    for (int mt = 0; mt < 2; mt++) {
                        mma_f16(acc[mt][nt], a[mt], &bhf[half*2]);
                        mma_f16(acc[mt][nt], a[mt], &blf[half*2]);
                    }
                }
            }
        }
        __syncthreads();
    }

    // --- epilogue ---
#pragma unroll
    for (int mt = 0; mt < 2; mt++) {
#pragma unroll
        for (int nt = 0; nt < 8; nt++) {
#pragma unroll
            for (int rr = 0; rr < 2; rr++) {
                int m   = m0 + wm*32 + mt*16 + g + rr*8;
                int col = wn*64 + nt*8 + tg*2;
                float y0 = acc[mt][nt][rr*2+0];
                float y1 = acc[mt][nt][rr*2+1];
                int hh = col >> 5, d = col & 31;
                int si = m >> 8,  j = m & 255;
                size_t idx = (((size_t)si*HH + hh)*SS + j)*DD + d;
                if (mode == 0) {
                    if (ny == 0) {
                        y0 *= 0.17677669529663687f; y1 *= 0.17677669529663687f;
                        __half2 vh, vl;
                        split2h(y0, vh.x, vl.x);
                        split2h(y1, vh.y, vl.y);
                        *(__half2*)&g_Qh[idx] = vh;
                        *(__half2*)&g_Ql[idx] = vl;
                    } else {
                        float s0 = 1.f/(1.f + __expf(-(y0 + bg[col])));
                        float s1 = 1.f/(1.f + __expf(-(y1 + bg[col+1])));
                        *(float2*)(g_G + (size_t)m*CC + col) = make_float2(s0, s1);
                    }
                } else {
                    __half2 v = __floats2half2_rn(y0, y1);
                    if (ny == 0) *(__half2*)&g_K[idx] = v;
                    else         *(__half2*)&g_V[idx] = v;
                }
            }
        }
    }
}

// ---------------- output projection (fp16 2-term, A = g_O) ----------------
__global__ void __launch_bounds__(256, 2) proj2(const float* __restrict__ bo,
                                                float* __restrict__ outp)
{
    extern __shared__ __half sm[];
    __half* As = sm;
    __half* Bh = sm + 128*AST;
    __half* Bl = sm + 2*128*AST;

    const int tid = threadIdx.x;
    const int lane = tid & 31;
    const int w = tid >> 5;
    const int g = lane >> 2;
    const int tg = lane & 3;
    const int wm = w & 3;
    const int wn = w >> 2;
    const int m0 = blockIdx.x * 128;

    const int arow = ((lane >> 3) & 1) * 8 + (lane & 7);
    const int acol = (lane >> 4) * 8;
    const int brow = (lane >> 4) * 8 + (lane & 7);
    const int bcol = ((lane >> 3) & 1) * 8;

    float acc[2][8][4];
#pragma unroll
    for (int a = 0; a < 2; a++)
#pragma unroll
        for (int b = 0; b < 8; b++)
#pragma unroll
            for (int c = 0; c < 4; c++) acc[a][b][c] = 0.f;

    for (int ks = 0; ks < 2; ks++) {
        const int kbase = ks * 64;
#pragma unroll
        for (int i = 0; i < 16; i++) {
            int lin = tid + 256*i;
            int r = lin >> 5;
            int c = (lin & 31) * 2;
            *(u32*)&As[r*AST+c] = *(const u32*)(g_O + (size_t)(m0+r)*CC + kbase + c);
        }
#pragma unroll
        for (int i = 0; i < 16; i++) {
            int lin = tid + 256*i;
            int r = lin >> 5;
            int c = (lin & 31) * 2;
            *(u32*)&Bh[r*AST+c] = *(const u32*)(g_Wo_h + (size_t)r*CC + kbase + c);
            *(u32*)&Bl[r*AST+c] = *(const u32*)(g_Wo_l + (size_t)r*CC + kbase + c);
        }
        __syncthreads();

#pragma unroll
        for (int k16 = 0; k16 < 4; k16++) {
            const int k0 = k16 * 16;
            u32 a[2][4];
#pragma unroll
            for (int mt = 0; mt < 2; mt++)
                ldsm4(a[mt], &As[(wm*32 + mt*16 + arow)*AST + k0 + acol]);
#pragma unroll
            for (int np = 0; np < 4; np++) {
                u32 bhf[4], blf[4];
                ldsm4(bhf, &Bh[(wn*64 + np*16 + brow)*AST + k0 + bcol]);
                ldsm4(blf, &Bl[(wn*64 + np*16 + brow)*AST + k0 + bcol]);
#pragma unroll
                for (int half = 0; half < 2; half++) {
                    int nt = 2*np + half;
#pragma unroll
                    for (int mt = 0; mt < 2; mt++) {
                        mma_f16(acc[mt][nt], a[mt], &bhf[half*2]);
                        mma_f16(acc[mt][nt], a[mt], &blf[half*2]);
                    }
                }
            }
        }
        __syncthreads();
    }

#pragma unroll
    for (int mt = 0; mt < 2; mt++) {
#pragma unroll
        for (int nt = 0; nt < 8; nt++) {
#pragma unroll
            for (int rr = 0; rr < 2; rr++) {
                int m   = m0 + wm*32 + mt*16 + g + rr*8;
                int col = wn*64 + nt*8 + tg*2;
                float2 o;
                o.x = acc[mt][nt][rr*2+0] + bo[col];
                o.y = acc[mt][nt][rr*2+1] + bo[col+1];
                *(float2*)(outp + (size_t)m*CC + col) = o;
            }
        }
    }
}

// ---------------- attention v8: P single fp16 term in P·V ----------------
#define KST 40
#define ATTN_SMEM (2*256*KST*2 + 256*4)   // 41984 B

__global__ void __launch_bounds__(256, 2) attn_kernel(const float* __restrict__ bias2)
{
    extern __shared__ char smraw[];
    __half* Ksh = (__half*)smraw;                 // [256][KST]
    __half* Vsh = Ksh + 256*KST;                  // [256][KST]  (k rows, d cols)
    float*  b2s = (float*)(Vsh + 256*KST);        // [256]

    const int tid = threadIdx.x, lane = tid & 31, w = tid >> 5;
    const int g = lane >> 2, tg = lane & 3;
    const int h = blockIdx.x, s = blockIdx.y;
    const size_t headBase = ((size_t)s*HH + h) * SS * DD;

    // ---- stage K and V (both coalesced uint4, same layout) ----
    {
        const uint4* kh4 = (const uint4*)(g_K + headBase);
        const uint4* vh4 = (const uint4*)(g_V + headBase);
#pragma unroll
        for (int it = 0; it < 4; it++) {
            int i = tid + it*256;
            int row = i >> 2, q4 = i & 3;
            *(uint4*)&Ksh[row*KST + q4*8] = kh4[i];
            *(uint4*)&Vsh[row*KST + q4*8] = vh4[i];
        }
    }
    b2s[tid] = bias2[(size_t)s*SS + tid];

    // ---- Q fragments (split), overlap staging ----
    const int q0 = w * 32;
    u32 qh[2][2][4], ql[2][2][4];
    {
        const u32* srcH = (const u32*)(g_Qh + headBase);
        const u32* srcL = (const u32*)(g_Ql + headBase);
#pragma unroll
        for (int mt = 0; mt < 2; mt++) {
            int r0 = q0 + mt*16 + g, r1 = r0 + 8;
#pragma unroll
            for (int sl2 = 0; sl2 < 2; sl2++) {
                int kc = sl2*8 + tg;
                qh[mt][sl2][0] = srcH[r0*16 + kc];
                qh[mt][sl2][1] = srcH[r1*16 + kc];
                qh[mt][sl2][2] = srcH[r0*16 + kc + 4];
                qh[mt][sl2][3] = srcH[r1*16 + kc + 4];
                ql[mt][sl2][0] = srcL[r0*16 + kc];
                ql[mt][sl2][1] = srcL[r1*16 + kc];
                ql[mt][sl2][2] = srcL[r0*16 + kc + 4];
                ql[mt][sl2][3] = srcL[r1*16 + kc + 4];
            }
        }
    }
    __syncthreads();

    float acc[2][4][4];
#pragma unroll
    for (int mt = 0; mt < 2; mt++)
#pragma unroll
        for (int a = 0; a < 4; a++)
#pragma unroll
            for (int b = 0; b < 4; b++) acc[mt][a][b] = 0.f;
    float m_a[2] = {-1e30f, -1e30f}, m_b[2] = {-1e30f, -1e30f};
    float l_a[2] = {0.f, 0.f},       l_b[2] = {0.f, 0.f};

    const int kr = lane & 7, kcb = lane >> 3;
    const int vrow = ((lane >> 3) & 1) * 8 + (lane & 7);   // trans ldsm2 row

    const float4* pb1base = (const float4*)(g_pb1 + ((((size_t)h*8 + w)*8)*8*32 + lane)*4);

#pragma unroll
    for (int c4 = 0; c4 < 8; c4++) {                   // 8 chunks of 32 keys
        const int n0c = c4 * 32;
        const float4* pb = pb1base + (size_t)c4 * 256;
        // ---- QK^T ----
        float sc[2][4][4];
#pragma unroll
        for (int mt = 0; mt < 2; mt++)
#pragma unroll
            for (int nt = 0; nt < 4; nt++)
#pragma unroll
                for (int c = 0; c < 4; c++) sc[mt][nt][c] = 0.f;

#pragma unroll
        for (int nt = 0; nt < 4; nt++) {
            int n8 = n0c + nt*8;
            u32 kb[4];
            ldsm4(kb, &Ksh[(n8 + kr)*KST + kcb*8]);
#pragma unroll
            for (int mt = 0; mt < 2; mt++) {
#pragma unroll
                for (int sl2 = 0; sl2 < 2; sl2++) {
                    mma_f16(sc[mt][nt], qh[mt][sl2], &kb[sl2*2]);
                    mma_f16(sc[mt][nt], ql[mt][sl2], &kb[sl2*2]);
                }
            }
        }

        // ---- bias add (fragment-ordered) + per-row max, rescale ----
#pragma unroll
        for (int mt = 0; mt < 2; mt++) {
            float ta = -1e30f, tb = -1e30f;
#pragma unroll
            for (int np = 0; np < 2; np++) {
                float4 fa = pb[(mt*4 + np)*32];
                float4 fb = pb[(mt*4 + 2 + np)*32];
#pragma unroll
                for (int half = 0; half < 2; half++) {
                    int nt = 2*np + half;
                    int c = n0c + nt*8 + tg*2;
                    float2 b2v = *(float2*)&b2s[c];
                    float bax = half ? fa.z : fa.x;
                    float bay = half ? fa.w : fa.y;
                    float bbx = half ? fb.z : fb.x;
                    float bby = half ? fb.w : fb.y;
                    sc[mt][nt][0] += bax + b2v.x;
                    sc[mt][nt][1] += bay + b2v.y;
                    sc[mt][nt][2] += bbx + b2v.x;
                    sc[mt][nt][3] += bby + b2v.y;
                    ta = fmaxf(ta, fmaxf(sc[mt][nt][0], sc[mt][nt][1]));
                    tb = fmaxf(tb, fmaxf(sc[mt][nt][2], sc[mt][nt][3]));
                }
            }
            ta = fmaxf(ta, __shfl_xor_sync(0xffffffffu, ta, 1));
            ta = fmaxf(ta, __shfl_xor_sync(0xffffffffu, ta, 2));
            tb = fmaxf(tb, __shfl_xor_sync(0xffffffffu, tb, 1));
            tb = fmaxf(tb, __shfl_xor_sync(0xffffffffu, tb, 2));

            float mna = fmaxf(m_a[mt], ta), mnb = fmaxf(m_b[mt], tb);
            float sca = __expf(m_a[mt] - mna), scb = __expf(m_b[mt] - mnb);
            m_a[mt] = mna; m_b[mt] = mnb;
            l_a[mt] *= sca; l_b[mt] *= scb;
#pragma unroll
            for (int nd = 0; nd < 4; nd++) {
                acc[mt][nd][0] *= sca; acc[mt][nd][1] *= sca;
                acc[mt][nd][2] *= scb; acc[mt][nd][3] *= scb;
            }
        }

        // ---- fused exp + single-fp16 pack + P·V per k16 ----
#pragma unroll
        for (int s8 = 0; s8 < 2; s8++) {
            u32 ah[2][4];
#pragma unroll
            for (int mt = 0; mt < 2; mt++) {
#pragma unroll
                for (int half = 0; half < 2; half++) {
                    int nt = 2*s8 + half;
                    float p0 = __expf(sc[mt][nt][0] - m_a[mt]);
                    float p1 = __expf(sc[mt][nt][1] - m_a[mt]);
                    float p2 = __expf(sc[mt][nt][2] - m_b[mt]);
                    float p3 = __expf(sc[mt][nt][3] - m_b[mt]);
                    l_a[mt] += p0 + p1;
                    l_b[mt] += p2 + p3;
                    __half2 h01 = __floats2half2_rn(p0, p1);
                    __half2 h23 = __floats2half2_rn(p2, p3);
                    ah[mt][half*2]     = *(u32*)&h01;
                    ah[mt][half*2 + 1] = *(u32*)&h23;
                }
            }
            int kkg = n0c + s8*16;
#pragma unroll
            for (int nd = 0; nd < 4; nd++) {
                u32 vb[2];
                ldsm2t(vb, &Vsh[(kkg + vrow)*KST + nd*8]);
#pragma unroll
                for (int mt = 0; mt < 2; mt++) {
                    mma_f16(acc[mt][nd], ah[mt], vb);
                }
            }
        }
    }

    // ---- reduce row-sums, epilogue: normalize, gate, fp16 store ----
#pragma unroll
    for (int mt = 0; mt < 2; mt++) {
        float la = l_a[mt], lb = l_b[mt];
        la += __shfl_xor_sync(0xffffffffu, la, 1);
        la += __shfl_xor_sync(0xffffffffu, la, 2);
        lb += __shfl_xor_sync(0xffffffffu, lb, 1);
        lb += __shfl_xor_sync(0xffffffffu, lb, 2);
        const float inva = 1.0f / la;
        const float invb = 1.0f / lb;
        const int ta_t = s*SS + q0 + mt*16 + g;
        const int tb_t = ta_t + 8;
#pragma unroll
        for (int nd = 0; nd < 4; nd++) {
            int col = h*DD + nd*8 + tg*2;
            float2 ga = *(const float2*)(g_G + (size_t)ta_t*CC + col);
            float2 gb = *(const float2*)(g_G + (size_t)tb_t*CC + col);
            float o0 = acc[mt][nd][0] * inva * ga.x;
            float o1 = acc[mt][nd][1] * inva * ga.y;
            float o2 = acc[mt][nd][2] * invb * gb.x;
            float o3 = acc[mt][nd][3] * invb * gb.y;
            *(__half2*)&g_O[(size_t)ta_t*CC + col] = __floats2half2_rn(o0, o1);
            *(__half2*)&g_O[(size_t)tb_t*CC + col] = __floats2half2_rn(o2, o3);
        }
    }
}

// ---------------- launch ----------------
extern "C" void kernel_launch(void* const* d_in, const int* in_sizes, int n_in,
                              void* d_out, int out_size)
{
    const float* q_x   = (const float*)d_in[0];
    const float* kv_x  = (const float*)d_in[1];
    const float* bias1 = (const float*)d_in[2];
    const float* bias2 = (const float*)d_in[3];
    const float* bg    = (const float*)d_in[8];
    const float* bo    = (const float*)d_in[10];
    float* out = (float*)d_out;

    cudaFuncSetAttribute(proj01,      cudaFuncAttributeMaxDynamicSharedMemorySize, PROJ_SMEM);
    cudaFuncSetAttribute(proj2,       cudaFuncAttributeMaxDynamicSharedMemorySize, PROJ_SMEM);
    cudaFuncSetAttribute(attn_kernel, cudaFuncAttributeMaxDynamicSharedMemorySize, ATTN_SMEM);

    prep_all<<<1024, 256>>>((const float*)d_in[4], (const float*)d_in[5],
                            (const float*)d_in[6], (const float*)d_in[7],
                            (const float*)d_in[9], bias1);
    proj01<<<dim3(512, 4), 256, PROJ_SMEM>>>(q_x, kv_x, bg);
    attn_kernel<<<dim3(HH, SS), 256, ATTN_SMEM>>>(bias2);
    proj2<<<512, 256, PROJ_SMEM>>>(bo, out);
}

// round 15
// speedup vs baseline: 1.8489x; 1.0662x over previous
#include <cuda_runtime.h>
#include <cuda_fp16.h>

#define SS 256
#define CC 128
#define HH 4
#define DD 32
#define TT (SS*SS)

typedef unsigned int u32;

// ---------------- global scratch (no allocations allowed) ----------------
#define NQ (SS*HH*SS*DD)   // 8,388,608
__device__ __half g_Q [NQ];                    // Q single fp16 (A operand of QK^T)
__device__ __half g_K [NQ];                    // K single fp16
__device__ __half g_V [NQ];                    // V single fp16
__device__ float  g_G [(size_t)TT*CC];
__device__ __half g_O [(size_t)TT*CC];         // attn output single fp16
__device__ __half g_Wqg_h[2*CC*CC], g_Wqg_l[2*CC*CC];   // weights split
__device__ __half g_Wkv_h[2*CC*CC], g_Wkv_l[2*CC*CC];
__device__ __half g_Wo_h [CC*CC],   g_Wo_l [CC*CC];
// fragment-ordered bias1 permutation: [h][w][c4][i][lane][4]
__device__ float  g_pb1[4*8*8*8*32*4];         // 1 MB

__device__ __forceinline__ void split2h(float v, __half& h, __half& l) {
    h = __float2half_rn(v);
    l = __float2half_rn(v - __half2float(h));
}

__device__ __forceinline__ void mma_f16(float* d, const u32* a, const u32* b) {
    asm volatile(
      "mma.sync.aligned.m16n8k16.row.col.f32.f16.f16.f32 "
      "{%0,%1,%2,%3}, {%4,%5,%6,%7}, {%8,%9}, {%0,%1,%2,%3};\n"
      : "+f"(d[0]), "+f"(d[1]), "+f"(d[2]), "+f"(d[3])
      : "r"(a[0]), "r"(a[1]), "r"(a[2]), "r"(a[3]), "r"(b[0]), "r"(b[1]));
}

__device__ __forceinline__ void ldsm4(u32* r, const void* p) {
    u32 a = (u32)__cvta_generic_to_shared(p);
    asm volatile("ldmatrix.sync.aligned.m8n8.x4.shared.b16 {%0,%1,%2,%3}, [%4];"
                 : "=r"(r[0]), "=r"(r[1]), "=r"(r[2]), "=r"(r[3]) : "r"(a));
}
__device__ __forceinline__ void ldsm2t(u32* r, const void* p) {
    u32 a = (u32)__cvta_generic_to_shared(p);
    asm volatile("ldmatrix.sync.aligned.m8n8.x2.trans.shared.b16 {%0,%1}, [%2];"
                 : "=r"(r[0]), "=r"(r[1]) : "r"(a));
}

// ---------------- merged prep: weights split + bias1 permutation ----------
__global__ void prep_all(const float* __restrict__ wq, const float* __restrict__ wk,
                         const float* __restrict__ wv, const float* __restrict__ wg,
                         const float* __restrict__ wo, const float* __restrict__ bias1) {
    int idx = blockIdx.x * 256 + threadIdx.x;   // 262144 total
    if (idx < CC*CC) {
        int i = idx;
        split2h(wq[i], g_Wqg_h[i],         g_Wqg_l[i]);
        split2h(wg[i], g_Wqg_h[CC*CC + i], g_Wqg_l[CC*CC + i]);
        split2h(wk[i], g_Wkv_h[i],         g_Wkv_l[i]);
        split2h(wv[i], g_Wkv_h[CC*CC + i], g_Wkv_l[CC*CC + i]);
        split2h(wo[i], g_Wo_h[i],          g_Wo_l[i]);
    }
    // bias1 permutation: flat j = mt*16 + rowsel*8 + nt*2 + colpair
    int x    = idx & 3;
    int lane = (idx >> 2) & 31;
    int i4   = (idx >> 7) & 7;
    int c4   = (idx >> 10) & 7;
    int w    = (idx >> 13) & 7;
    int h    = idx >> 16;
    int j = i4*4 + x;
    int colpair = j & 1;
    int nt      = (j >> 1) & 3;
    int rowsel  = (j >> 3) & 1;
    int mt      = (j >> 4) & 1;
    int g = lane >> 2, tg = lane & 3;
    int q = w*32 + mt*16 + rowsel*8 + g;
    int k = c4*32 + nt*8 + tg*2 + colpair;
    g_pb1[idx] = bias1[((size_t)h*SS + q)*SS + k];
}

// ---------------- fused input projection (fp16 2-term: A single, W split) --
// grid (512, 4): mode = blockIdx.y>>1 (0: q_x->[Wq;Wg], 1: kv_x->[Wk;Wv]),
//                ny = blockIdx.y&1 (N-half).
#define AST 72
#define PROJ_SMEM (3*128*AST*2)   // 55296 B

__global__ void __launch_bounds__(256, 2) proj01(const float* __restrict__ q_x,
                                                 const float* __restrict__ kv_x,
                                                 const float* __restrict__ bg)
{
    extern __shared__ __half sm[];
    __half* As = sm;
    __half* Bh = sm + 128*AST;
    __half* Bl = sm + 2*128*AST;

    const int tid = threadIdx.x;
    const int lane = tid & 31;
    const int w = tid >> 5;
    const int g = lane >> 2;
    const int tg = lane & 3;
    const int wm = w & 3;
    const int wn = w >> 2;
    const int m0 = blockIdx.x * 128;
    const int mode = blockIdx.y >> 1;
    const int ny = blockIdx.y & 1;
    const int n0 = ny * 128;

    const int arow = ((lane >> 3) & 1) * 8 + (lane & 7);
    const int acol = (lane >> 4) * 8;
    const int brow = (lane >> 4) * 8 + (lane & 7);
    const int bcol = ((lane >> 3) & 1) * 8;

    const float* X = mode ? kv_x : q_x;
    const __half* Wh = mode ? g_Wkv_h : g_Wqg_h;
    const __half* Wl = mode ? g_Wkv_l : g_Wqg_l;

    float acc[2][8][4];
#pragma unroll
    for (int a = 0; a < 2; a++)
#pragma unroll
        for (int b = 0; b < 8; b++)
#pragma unroll
            for (int c = 0; c < 4; c++) acc[a][b][c] = 0.f;

    for (int ks = 0; ks < 2; ks++) {
        const int kbase = ks * 64;
#pragma unroll
        for (int i = 0; i < 8; i++) {
            int lin = tid + 256*i;
            int r = lin >> 4;
            int c = (lin & 15) * 4;
            float4 xv = *(const float4*)(X + (size_t)(m0+r)*CC + kbase + c);
            __half2 p01 = __floats2half2_rn(xv.x, xv.y);
            __half2 p23 = __floats2half2_rn(xv.z, xv.w);
            *(u32*)&As[r*AST+c]   = *(u32*)&p01;
            *(u32*)&As[r*AST+c+2] = *(u32*)&p23;
        }
#pragma unroll
        for (int i = 0; i < 16; i++) {
            int lin = tid + 256*i;
            int r = lin >> 5;
            int c = (lin & 31) * 2;
            *(u32*)&Bh[r*AST+c] = *(const u32*)(Wh + (size_t)(n0+r)*CC + kbase + c);
            *(u32*)&Bl[r*AST+c] = *(const u32*)(Wl + (size_t)(n0+r)*CC + kbase + c);
        }
        __syncthreads();

#pragma unroll
        for (int k16 = 0; k16 < 4; k16++) {
            const int k0 = k16 * 16;
            u32 a[2][4];
#pragma unroll
            for (int mt = 0; mt < 2; mt++)
                ldsm4(a[mt], &As[(wm*32 + mt*16 + arow)*AST + k0 + acol]);
#pragma unroll
            for (int np = 0; np < 4; np++) {
                u32 bhf[4], blf[4];
                ldsm4(bhf, &Bh[(wn*64 + np*16 + brow)*AST + k0 + bcol]);
                ldsm4(blf, &Bl[(wn*64 + np*16 + brow)*AST + k0 + bcol]);
#pragma unroll
                for (int half = 0; half < 2; half++) {
                    int nt = 2*np + half;
#pragma unroll
                    for (int mt = 0; mt < 2; mt++) {
                        mma_f16(acc[mt][nt], a[mt], &bhf[half*2]);
                        mma_f16(acc[mt][nt], a[mt], &blf[half*2]);
                    }
                }
            }
        }
        __syncthreads();
    }

    // --- epilogue ---
#pragma unroll
    for (int mt = 0; mt < 2; mt++) {
#pragma unroll
        for (int nt = 0; nt < 8; nt++) {
#pragma unroll
            for (int rr = 0; rr < 2; rr++) {
                int m   = m0 + wm*32 + mt*16 + g + rr*8;
                int col = wn*64 + nt*8 + tg*2;
                float y0 = acc[mt][nt][rr*2+0];
                float y1 = acc[mt][nt][rr*2+1];
                int hh = col >> 5, d = col & 31;
                int si = m >> 8,  j = m & 255;
                size_t idx = (((size_t)si*HH + hh)*SS + j)*DD + d;
                if (mode == 0) {
                    if (ny == 0) {
                        y0 *= 0.17677669529663687f; y1 *= 0.17677669529663687f;
                        *(__half2*)&g_Q[idx] = __floats2half2_rn(y0, y1);
                    } else {
                        float s0 = 1.f/(1.f + __expf(-(y0 + bg[col])));
                        float s1 = 1.f/(1.f + __expf(-(y1 + bg[col+1])));
                        *(float2*)(g_G + (size_t)m*CC + col) = make_float2(s0, s1);
                    }
                } else {
                    __half2 v = __floats2half2_rn(y0, y1);
                    if (ny == 0) *(__half2*)&g_K[idx] = v;
                    else         *(__half2*)&g_V[idx] = v;
                }
            }
        }
    }
}

// ---------------- output projection (fp16 2-term, A = g_O) ----------------
__global__ void __launch_bounds__(256, 2) proj2(const float* __restrict__ bo,
                                                float* __restrict__ outp)
{
    extern __shared__ __half sm[];
    __half* As = sm;
    __half* Bh = sm + 128*AST;
    __half* Bl = sm + 2*128*AST;

    const int tid = threadIdx.x;
    const int lane = tid & 31;
    const int w = tid >> 5;
    const int g = lane >> 2;
    const int tg = lane & 3;
    const int wm = w & 3;
    const int wn = w >> 2;
    const int m0 = blockIdx.x * 128;

    const int arow = ((lane >> 3) & 1) * 8 + (lane & 7);
    const int acol = (lane >> 4) * 8;
    const int brow = (lane >> 4) * 8 + (lane & 7);
    const int bcol = ((lane >> 3) & 1) * 8;

    float acc[2][8][4];
#pragma unroll
    for (int a = 0; a < 2; a++)
#pragma unroll
        for (int b = 0; b < 8; b++)
#pragma unroll
            for (int c = 0; c < 4; c++) acc[a][b][c] = 0.f;

    for (int ks = 0; ks < 2; ks++) {
        const int kbase = ks * 64;
#pragma unroll
        for (int i = 0; i < 16; i++) {
            int lin = tid + 256*i;
            int r = lin >> 5;
            int c = (lin & 31) * 2;
            *(u32*)&As[r*AST+c] = *(const u32*)(g_O + (size_t)(m0+r)*CC + kbase + c);
        }
#pragma unroll
        for (int i = 0; i < 16; i++) {
            int lin = tid + 256*i;
            int r = lin >> 5;
            int c = (lin & 31) * 2;
            *(u32*)&Bh[r*AST+c] = *(const u32*)(g_Wo_h + (size_t)r*CC + kbase + c);
            *(u32*)&Bl[r*AST+c] = *(const u32*)(g_Wo_l + (size_t)r*CC + kbase + c);
        }
        __syncthreads();

#pragma unroll
        for (int k16 = 0; k16 < 4; k16++) {
            const int k0 = k16 * 16;
            u32 a[2][4];
#pragma unroll
            for (int mt = 0; mt < 2; mt++)
                ldsm4(a[mt], &As[(wm*32 + mt*16 + arow)*AST + k0 + acol]);
#pragma unroll
            for (int np = 0; np < 4; np++) {
                u32 bhf[4], blf[4];
                ldsm4(bhf, &Bh[(wn*64 + np*16 + brow)*AST + k0 + bcol]);
                ldsm4(blf, &Bl[(wn*64 + np*16 + brow)*AST + k0 + bcol]);
#pragma unroll
                for (int half = 0; half < 2; half++) {
                    int nt = 2*np + half;
#pragma unroll
                    for (int mt = 0; mt < 2; mt++) {
                        mma_f16(acc[mt][nt], a[mt], &bhf[half*2]);
                        mma_f16(acc[mt][nt], a[mt], &blf[half*2]);
                    }
                }
            }
        }
        __syncthreads();
    }

#pragma unroll
    for (int mt = 0; mt < 2; mt++) {
#pragma unroll
        for (int nt = 0; nt < 8; nt++) {
#pragma unroll
            for (int rr = 0; rr < 2; rr++) {
                int m   = m0 + wm*32 + mt*16 + g + rr*8;
                int col = wn*64 + nt*8 + tg*2;
                float2 o;
                o.x = acc[mt][nt][rr*2+0] + bo[col];
                o.y = acc[mt][nt][rr*2+1] + bo[col+1];
                *(float2*)(outp + (size_t)m*CC + col) = o;
            }
        }
    }
}

// ---------------- attention v9: single-fp16 Q, K, V, P ----------------
#define KST 40
#define ATTN_SMEM (2*256*KST*2 + 256*4)   // 41984 B

__global__ void __launch_bounds__(256, 2) attn_kernel(const float* __restrict__ bias2)
{
    extern __shared__ char smraw[];
    __half* Ksh = (__half*)smraw;                 // [256][KST]
    __half* Vsh = Ksh + 256*KST;                  // [256][KST]  (k rows, d cols)
    float*  b2s = (float*)(Vsh + 256*KST);        // [256]

    const int tid = threadIdx.x, lane = tid & 31, w = tid >> 5;
    const int g = lane >> 2, tg = lane & 3;
    const int h = blockIdx.x, s = blockIdx.y;
    const size_t headBase = ((size_t)s*HH + h) * SS * DD;

    // ---- stage K and V (both coalesced uint4, same layout) ----
    {
        const uint4* kh4 = (const uint4*)(g_K + headBase);
        const uint4* vh4 = (const uint4*)(g_V + headBase);
#pragma unroll
        for (int it = 0; it < 4; it++) {
            int i = tid + it*256;
            int row = i >> 2, q4 = i & 3;
            *(uint4*)&Ksh[row*KST + q4*8] = kh4[i];
            *(uint4*)&Vsh[row*KST + q4*8] = vh4[i];
        }
    }
    b2s[tid] = bias2[(size_t)s*SS + tid];

    // ---- Q fragments (single fp16), overlap staging ----
    const int q0 = w * 32;
    u32 qf[2][2][4];
    {
        const u32* srcH = (const u32*)(g_Q + headBase);
#pragma unroll
        for (int mt = 0; mt < 2; mt++) {
            int r0 = q0 + mt*16 + g, r1 = r0 + 8;
#pragma unroll
            for (int sl2 = 0; sl2 < 2; sl2++) {
                int kc = sl2*8 + tg;
                qf[mt][sl2][0] = srcH[r0*16 + kc];
                qf[mt][sl2][1] = srcH[r1*16 + kc];
                qf[mt][sl2][2] = srcH[r0*16 + kc + 4];
                qf[mt][sl2][3] = srcH[r1*16 + kc + 4];
            }
        }
    }
    __syncthreads();

    float acc[2][4][4];
#pragma unroll
    for (int mt = 0; mt < 2; mt++)
#pragma unroll
        for (int a = 0; a < 4; a++)
#pragma unroll
            for (int b = 0; b < 4; b++) acc[mt][a][b] = 0.f;
    float m_a[2] = {-1e30f, -1e30f}, m_b[2] = {-1e30f, -1e30f};
    float l_a[2] = {0.f, 0.f},       l_b[2] = {0.f, 0.f};

    const int kr = lane & 7, kcb = lane >> 3;
    const int vrow = ((lane >> 3) & 1) * 8 + (lane & 7);   // trans ldsm2 row

    const float4* pb1base = (const float4*)(g_pb1 + ((((size_t)h*8 + w)*8)*8*32 + lane)*4);

#pragma unroll
    for (int c4 = 0; c4 < 8; c4++) {                   // 8 chunks of 32 keys
        const int n0c = c4 * 32;
        const float4* pb = pb1base + (size_t)c4 * 256;
        // ---- QK^T (single-term) ----
        float sc[2][4][4];
#pragma unroll
        for (int mt = 0; mt < 2; mt++)
#pragma unroll
            for (int nt = 0; nt < 4; nt++)
#pragma unroll
                for (int c = 0; c < 4; c++) sc[mt][nt][c] = 0.f;

#pragma unroll
        for (int nt = 0; nt < 4; nt++) {
            int n8 = n0c + nt*8;
            u32 kb[4];
            ldsm4(kb, &Ksh[(n8 + kr)*KST + kcb*8]);
#pragma unroll
            for (int mt = 0; mt < 2; mt++) {
#pragma unroll
                for (int sl2 = 0; sl2 < 2; sl2++) {
                    mma_f16(sc[mt][nt], qf[mt][sl2], &kb[sl2*2]);
                }
            }
        }

        // ---- bias add (fragment-ordered) + per-row max, rescale ----
#pragma unroll
        for (int mt = 0; mt < 2; mt++) {
            float ta = -1e30f, tb = -1e30f;
#pragma unroll
            for (int np = 0; np < 2; np++) {
                float4 fa = pb[(mt*4 + np)*32];
                float4 fb = pb[(mt*4 + 2 + np)*32];
#pragma unroll
                for (int half = 0; half < 2; half++) {
                    int nt = 2*np + half;
                    int c = n0c + nt*8 + tg*2;
                    float2 b2v = *(float2*)&b2s[c];
                    float bax = half ? fa.z : fa.x;
                    float bay = half ? fa.w : fa.y;
                    float bbx = half ? fb.z : fb.x;
                    float bby = half ? fb.w : fb.y;
                    sc[mt][nt][0] += bax + b2v.x;
                    sc[mt][nt][1] += bay + b2v.y;
                    sc[mt][nt][2] += bbx + b2v.x;
                    sc[mt][nt][3] += bby + b2v.y;
                    ta = fmaxf(ta, fmaxf(sc[mt][nt][0], sc[mt][nt][1]));
                    tb = fmaxf(tb, fmaxf(sc[mt][nt][2], sc[mt][nt][3]));
                }
            }
            ta = fmaxf(ta, __shfl_xor_sync(0xffffffffu, ta, 1));
            ta = fmaxf(ta, __shfl_xor_sync(0xffffffffu, ta, 2));
            tb = fmaxf(tb, __shfl_xor_sync(0xffffffffu, tb, 1));
            tb = fmaxf(tb, __shfl_xor_sync(0xffffffffu, tb, 2));

            float mna = fmaxf(m_a[mt], ta), mnb = fmaxf(m_b[mt], tb);
            float sca = __expf(m_a[mt] - mna), scb = __expf(m_b[mt] - mnb);
            m_a[mt] = mna; m_b[mt] = mnb;
            l_a[mt] *= sca; l_b[mt] *= scb;
#pragma unroll
            for (int nd = 0; nd < 4; nd++) {
                acc[mt][nd][0] *= sca; acc[mt][nd][1] *= sca;
                acc[mt][nd][2] *= scb; acc[mt][nd][3] *= scb;
            }
        }

        // ---- fused exp + single-fp16 pack + P·V per k16 ----
#pragma unroll
        for (int s8 = 0; s8 < 2; s8++) {
            u32 ah[2][4];
#pragma unroll
            for (int mt = 0; mt < 2; mt++) {
#pragma unroll
                for (int half = 0; half < 2; half++) {
                    int nt = 2*s8 + half;
                    float p0 = __expf(sc[mt][nt][0] - m_a[mt]);
                    float p1 = __expf(sc[mt][nt][1] - m_a[mt]);
                    float p2 = __expf(sc[mt][nt][2] - m_b[mt]);
                    float p3 = __expf(sc[mt][nt][3] - m_b[mt]);
                    l_a[mt] += p0 + p1;
                    l_b[mt] += p2 + p3;
                    __half2 h01 = __floats2half2_rn(p0, p1);
                    __half2 h23 = __floats2half2_rn(p2, p3);
                    ah[mt][half*2]     = *(u32*)&h01;
                    ah[mt][half*2 + 1] = *(u32*)&h23;
                }
            }
            int kkg = n0c + s8*16;
#pragma unroll
            for (int nd = 0; nd < 4; nd++) {
                u32 vb[2];
                ldsm2t(vb, &Vsh[(kkg + vrow)*KST + nd*8]);
#pragma unroll
                for (int mt = 0; mt < 2; mt++) {
                    mma_f16(acc[mt][nd], ah[mt], vb);
                }
            }
        }
    }

    // ---- reduce row-sums, epilogue: normalize, gate, fp16 store ----
#pragma unroll
    for (int mt = 0; mt < 2; mt++) {
        float la = l_a[mt], lb = l_b[mt];
        la += __shfl_xor_sync(0xffffffffu, la, 1);
        la += __shfl_xor_sync(0xffffffffu, la, 2);
        lb += __shfl_xor_sync(0xffffffffu, lb, 1);
        lb += __shfl_xor_sync(0xffffffffu, lb, 2);
        const float inva = 1.0f / la;
        const float invb = 1.0f / lb;
        const int ta_t = s*SS + q0 + mt*16 + g;
        const int tb_t = ta_t + 8;
#pragma unroll
        for (int nd = 0; nd < 4; nd++) {
            int col = h*DD + nd*8 + tg*2;
            float2 ga = *(const float2*)(g_G + (size_t)ta_t*CC + col);
            float2 gb = *(const float2*)(g_G + (size_t)tb_t*CC + col);
            float o0 = acc[mt][nd][0] * inva * ga.x;
            float o1 = acc[mt][nd][1] * inva * ga.y;
            float o2 = acc[mt][nd][2] * invb * gb.x;
            float o3 = acc[mt][nd][3] * invb * gb.y;
            *(__half2*)&g_O[(size_t)ta_t*CC + col] = __floats2half2_rn(o0, o1);
            *(__half2*)&g_O[(size_t)tb_t*CC + col] = __floats2half2_rn(o2, o3);
        }
    }
}

// ---------------- launch ----------------
extern "C" void kernel_launch(void* const* d_in, const int* in_sizes, int n_in,
                              void* d_out, int out_size)
{
    const float* q_x   = (const float*)d_in[0];
    const float* kv_x  = (const float*)d_in[1];
    const float* bias1 = (const float*)d_in[2];
    const float* bias2 = (const float*)d_in[3];
    const float* bg    = (const float*)d_in[8];
    const float* bo    = (const float*)d_in[10];
    float* out = (float*)d_out;

    cudaFuncSetAttribute(proj01,      cudaFuncAttributeMaxDynamicSharedMemorySize, PROJ_SMEM);
    cudaFuncSetAttribute(proj2,       cudaFuncAttributeMaxDynamicSharedMemorySize, PROJ_SMEM);
    cudaFuncSetAttribute(attn_kernel, cudaFuncAttributeMaxDynamicSharedMemorySize, ATTN_SMEM);

    prep_all<<<1024, 256>>>((const float*)d_in[4], (const float*)d_in[5],
                            (const float*)d_in[6], (const float*)d_in[7],
                            (const float*)d_in[9], bias1);
    proj01<<<dim3(512, 4), 256, PROJ_SMEM>>>(q_x, kv_x, bg);
    attn_kernel<<<dim3(HH, SS), 256, ATTN_SMEM>>>(bias2);
    proj2<<<512, 256, PROJ_SMEM>>>(bo, out);
}